// round 1
// baseline (speedup 1.0000x reference)
#include <cuda_runtime.h>
#include <math.h>

// Problem constants
#define LL 103
#define RR 512
#define BB 2
#define SS 512
#define DD 768
#define ROWS (LL*RR)        // 52736
#define NCOL (BB*SS)        // 1024
#define INV_SQRT_D 0.03608439182435161269f

// Main-kernel tiling
#define TM 64
#define TN 128
#define KB 32
#define APITCH 772          // 768 + 4 pad (keeps float4 alignment, de-conflicts banks)
#define BPITCH 132          // 128 + 4 pad
#define SMEM_FLOATS (TM*APITCH + 2*KB*BPITCH)   // 49408 + 8448 = 57856
#define SMEM_BYTES (SMEM_FLOATS*4)              // 231424 <= 232448 limit

// ---------------- device scratch (static: no allocation allowed) -------------
__device__ float g_Mt[DD*DD];        // Mt[e][d'] = sum_k Wq[e,k]*Wk[d',k]
__device__ float g_fk2[NCOL*DD];     // fk2'[j][e] = inv*(output[j]·Mt[e] + c1[e])
__device__ float g_c1[DD];
__device__ float g_vbq[DD], g_vlaw[DD], g_vaccu[DD], g_vterm[DD];
__device__ float g_colb[NCOL], g_pvl[NCOL], g_pva[NCOL], g_pvt[NCOL];
__device__ float g_Tl[BB*ROWS], g_Ta[BB*ROWS], g_Tt[BB*ROWS];
__device__ float g_accu1v[BB*LL], g_term1v[BB*LL];

// ---------------- matvec: out[row] = M[row,:] . v  (row-major M, 768 cols) ---
__global__ void matvec_kernel(const float* __restrict__ M,
                              const float* __restrict__ v, int which)
{
    int row = blockIdx.x * 8 + (threadIdx.x >> 5);
    int lane = threadIdx.x & 31;
    if (row >= DD) return;
    float s = 0.f;
    for (int k = lane; k < DD; k += 32) s += M[(size_t)row*DD + k] * v[k];
    #pragma unroll
    for (int off = 16; off; off >>= 1) s += __shfl_xor_sync(0xffffffffu, s, off);
    if (lane == 0) {
        if      (which == 0) g_c1[row]    = s;
        else if (which == 1) g_vbq[row]   = s;
        else if (which == 2) g_vlaw[row]  = s;
        else if (which == 3) g_vaccu[row] = s;
        else                 g_vterm[row] = s;
    }
}

// ---------------- generic 64x64 NT GEMM (C[i,j] = f(sum_k A[i,k]B[j,k])) -----
// mode 0: B=Bp, C=g_Mt, alpha=1, no bias.   mode 1: B=g_Mt, C=g_fk2, alpha=inv, bias=g_c1.
__global__ __launch_bounds__(256) void nt_gemm64(const float* __restrict__ A,
                                                 const float* __restrict__ Bp,
                                                 int K, int N, int mode)
{
    __shared__ float As2[16*68];
    __shared__ float Bs2[16*68];
    const float* B = (mode == 0) ? Bp : g_Mt;
    float* C       = (mode == 0) ? g_Mt : g_fk2;
    const float alpha = (mode == 0) ? 1.0f : INV_SQRT_D;

    int tid = threadIdx.x;
    int tx = tid & 15, ty = tid >> 4;
    int j0 = blockIdx.x * 64, i0 = blockIdx.y * 64;
    float acc[4][4];
    #pragma unroll
    for (int i = 0; i < 4; i++)
        #pragma unroll
        for (int j = 0; j < 4; j++) acc[i][j] = 0.f;

    int row = tid >> 2, q = tid & 3;
    for (int kk = 0; kk < K; kk += 16) {
        __syncthreads();
        float4 va = *reinterpret_cast<const float4*>(&A[(size_t)(i0+row)*K + kk + q*4]);
        As2[(q*4+0)*68+row] = va.x; As2[(q*4+1)*68+row] = va.y;
        As2[(q*4+2)*68+row] = va.z; As2[(q*4+3)*68+row] = va.w;
        float4 vb = *reinterpret_cast<const float4*>(&B[(size_t)(j0+row)*K + kk + q*4]);
        Bs2[(q*4+0)*68+row] = vb.x; Bs2[(q*4+1)*68+row] = vb.y;
        Bs2[(q*4+2)*68+row] = vb.z; Bs2[(q*4+3)*68+row] = vb.w;
        __syncthreads();
        #pragma unroll
        for (int k = 0; k < 16; k++) {
            float4 a = *reinterpret_cast<const float4*>(&As2[k*68 + ty*4]);
            float4 b = *reinterpret_cast<const float4*>(&Bs2[k*68 + tx*4]);
            float av[4] = {a.x, a.y, a.z, a.w};
            float bv[4] = {b.x, b.y, b.z, b.w};
            #pragma unroll
            for (int i = 0; i < 4; i++)
                #pragma unroll
                for (int j = 0; j < 4; j++) acc[i][j] += av[i]*bv[j];
        }
    }
    #pragma unroll
    for (int i = 0; i < 4; i++)
        #pragma unroll
        for (int j = 0; j < 4; j++) {
            int cj = j0 + tx*4 + j;
            float b = (mode == 1) ? g_c1[cj] : 0.f;
            C[(size_t)(i0 + ty*4 + i)*N + cj] = alpha*(acc[i][j] + b);
        }
}

// ---------------- column bias + projected-V values per (b,s) -----------------
__global__ void colbias_kernel(const float* __restrict__ outp,
                               const int*   __restrict__ mask,
                               const float* __restrict__ bk, const float* __restrict__ bq,
                               const float* __restrict__ bv,
                               const float* __restrict__ wl, const float* __restrict__ wa,
                               const float* __restrict__ wt)
{
    int j = blockIdx.x;
    int tid = threadIdx.x;
    float s[8] = {0,0,0,0,0,0,0,0};
    for (int k = tid; k < DD; k += 256) {
        float o = outp[(size_t)j*DD + k];
        s[0] += o * g_vbq[k];
        s[1] += o * g_vlaw[k];
        s[2] += o * g_vaccu[k];
        s[3] += o * g_vterm[k];
        s[4] += bk[k]*bq[k];
        s[5] += bv[k]*wl[k];
        s[6] += bv[k]*wa[k];
        s[7] += bv[k]*wt[k];
    }
    __shared__ float red[8][8];
    int warp = tid >> 5, lane = tid & 31;
    #pragma unroll
    for (int v = 0; v < 8; v++) {
        float x = s[v];
        #pragma unroll
        for (int off = 16; off; off >>= 1) x += __shfl_xor_sync(0xffffffffu, x, off);
        if (lane == 0) red[v][warp] = x;
    }
    __syncthreads();
    if (tid == 0) {
        float t[8];
        #pragma unroll
        for (int v = 0; v < 8; v++) {
            float x = 0.f;
            #pragma unroll
            for (int w = 0; w < 8; w++) x += red[v][w];
            t[v] = x;
        }
        g_colb[j] = (t[0] + t[4]) * INV_SQRT_D + (1.0f - (float)mask[j]) * (-10000.0f);
        g_pvl[j] = t[1] + t[5];
        g_pva[j] = t[2] + t[6];
        g_pvt[j] = t[3] + t[7];
    }
}

// ---------------- main fused GEMM + online-softmax + 3 weighted sums ---------
__global__ __launch_bounds__(256, 1) void attn_kernel(
    const float* __restrict__ laws,
    const float* __restrict__ bld, const float* __restrict__ bad,
    const float* __restrict__ btd)
{
    extern __shared__ float sm[];
    float* As = sm;                       // [64][APITCH]
    float* Bs = sm + TM*APITCH;           // [2][KB][BPITCH]
    const int tid = threadIdx.x;
    const int tx = tid & 15, ty = tid >> 4;
    const int r0 = blockIdx.x * TM;

    // Load 64 laws rows into smem (coalesced, conflict-free)
    for (int idx = tid; idx < TM*192; idx += 256) {
        int row = idx / 192, q = idx - row*192;
        float4 v = *reinterpret_cast<const float4*>(&laws[(size_t)(r0+row)*DD + q*4]);
        float* dst = &As[row*APITCH + q*4];
        *reinterpret_cast<float4*>(dst) = v;
    }
    __syncthreads();

    const float bias_l = *bld, bias_a = *bad, bias_t = *btd;
    const float* Ap = &As[(ty*4)*APITCH];

    for (int bi = 0; bi < 2; bi++) {
        float mrun[4], Zr[4], Wlh[4], Wah[4], Wth[4];
        #pragma unroll
        for (int i = 0; i < 4; i++) { mrun[i] = -1e30f; Zr[i]=0.f; Wlh[i]=0.f; Wah[i]=0.f; Wth[i]=0.f; }

        for (int cc = 0; cc < 4; cc++) {
            const int j0 = bi*512 + cc*128;
            float acc[4][8];
            #pragma unroll
            for (int i = 0; i < 4; i++)
                #pragma unroll
                for (int u = 0; u < 8; u++) acc[i][u] = 0.f;

            // preload k-tile 0
            float4 pre[4];
            #pragma unroll
            for (int p = 0; p < 4; p++) {
                int flat = p*256 + tid; int row = flat >> 3, q = flat & 7;
                pre[p] = *reinterpret_cast<const float4*>(&g_fk2[(size_t)(j0+row)*DD + q*4]);
            }
            #pragma unroll
            for (int p = 0; p < 4; p++) {
                int flat = p*256 + tid; int row = flat >> 3, q = flat & 7;
                Bs[(q*4+0)*BPITCH+row] = pre[p].x;
                Bs[(q*4+1)*BPITCH+row] = pre[p].y;
                Bs[(q*4+2)*BPITCH+row] = pre[p].z;
                Bs[(q*4+3)*BPITCH+row] = pre[p].w;
            }
            int buf = 0;
            #pragma unroll 1
            for (int kt = 0; kt < 24; kt++) {
                __syncthreads();
                if (kt < 23) {
                    int kk = (kt+1)*KB;
                    #pragma unroll
                    for (int p = 0; p < 4; p++) {
                        int flat = p*256 + tid; int row = flat >> 3, q = flat & 7;
                        pre[p] = *reinterpret_cast<const float4*>(
                            &g_fk2[(size_t)(j0+row)*DD + kk + q*4]);
                    }
                }
                const float* Bb = &Bs[buf*(KB*BPITCH)];
                const float* Apk = Ap + kt*KB;
                #pragma unroll 8
                for (int k = 0; k < KB; k++) {
                    float av[4];
                    av[0] = Apk[0*APITCH + k];
                    av[1] = Apk[1*APITCH + k];
                    av[2] = Apk[2*APITCH + k];
                    av[3] = Apk[3*APITCH + k];
                    float4 b0 = *reinterpret_cast<const float4*>(&Bb[k*BPITCH + tx*4]);
                    float4 b1 = *reinterpret_cast<const float4*>(&Bb[k*BPITCH + 64 + tx*4]);
                    float bv[8] = {b0.x,b0.y,b0.z,b0.w,b1.x,b1.y,b1.z,b1.w};
                    #pragma unroll
                    for (int i = 0; i < 4; i++)
                        #pragma unroll
                        for (int u = 0; u < 8; u++) acc[i][u] += av[i]*bv[u];
                }
                if (kt < 23) {
                    float* d = &Bs[(buf^1)*(KB*BPITCH)];
                    #pragma unroll
                    for (int p = 0; p < 4; p++) {
                        int flat = p*256 + tid; int row = flat >> 3, q = flat & 7;
                        d[(q*4+0)*BPITCH+row] = pre[p].x;
                        d[(q*4+1)*BPITCH+row] = pre[p].y;
                        d[(q*4+2)*BPITCH+row] = pre[p].z;
                        d[(q*4+3)*BPITCH+row] = pre[p].w;
                    }
                    buf ^= 1;
                }
            }

            // ---- chunk epilogue: online softmax update ----
            float cb[8], pl[8], pa[8], pt[8];
            #pragma unroll
            for (int u = 0; u < 8; u++) {
                int j = j0 + ((u < 4) ? (tx*4 + u) : (64 + tx*4 + u - 4));
                cb[u] = g_colb[j]; pl[u] = g_pvl[j]; pa[u] = g_pva[j]; pt[u] = g_pvt[j];
            }
            #pragma unroll
            for (int i = 0; i < 4; i++) {
                float lm = -1e30f;
                #pragma unroll
                for (int u = 0; u < 8; u++) {
                    acc[i][u] += cb[u];
                    lm = fmaxf(lm, acc[i][u]);
                }
                #pragma unroll
                for (int off = 1; off < 16; off <<= 1)
                    lm = fmaxf(lm, __shfl_xor_sync(0xffffffffu, lm, off));
                float nm = fmaxf(mrun[i], lm);
                float sc = __expf(mrun[i] - nm);
                mrun[i] = nm;
                float z = 0.f, w0 = 0.f, w1 = 0.f, w2 = 0.f;
                #pragma unroll
                for (int u = 0; u < 8; u++) {
                    float e = __expf(acc[i][u] - nm);
                    z += e; w0 += e*pl[u]; w1 += e*pa[u]; w2 += e*pt[u];
                }
                Zr[i]  = Zr[i]*sc + z;
                Wlh[i] = Wlh[i]*sc + w0;
                Wah[i] = Wah[i]*sc + w1;
                Wth[i] = Wth[i]*sc + w2;
            }
        }

        // ---- finalize this b: cross-lane sums, tanh, store ----
        #pragma unroll
        for (int i = 0; i < 4; i++) {
            float z = Zr[i], w0 = Wlh[i], w1 = Wah[i], w2 = Wth[i];
            #pragma unroll
            for (int off = 1; off < 16; off <<= 1) {
                z  += __shfl_xor_sync(0xffffffffu, z,  off);
                w0 += __shfl_xor_sync(0xffffffffu, w0, off);
                w1 += __shfl_xor_sync(0xffffffffu, w1, off);
                w2 += __shfl_xor_sync(0xffffffffu, w2, off);
            }
            if (tx == 0) {
                int row = r0 + ty*4 + i;
                float inv = 1.0f / z;
                g_Tl[bi*ROWS + row] = tanhf(w0*inv + bias_l);
                g_Ta[bi*ROWS + row] = tanhf(w1*inv + bias_a);
                g_Tt[bi*ROWS + row] = tanhf(w2*inv + bias_t);
            }
        }
    }
}

// ---------------- reduce over r (512) per (b,l) ------------------------------
__global__ void head_reduce_kernel(const float* __restrict__ w1l, const float* __restrict__ b1l,
                                   const float* __restrict__ w1a, const float* __restrict__ b1a,
                                   const float* __restrict__ w1t, const float* __restrict__ b1t,
                                   float* __restrict__ out)
{
    int bl = blockIdx.x;
    int b = bl / LL, l = bl % LL;
    size_t base = (size_t)b*ROWS + (size_t)l*RR;
    int tid = threadIdx.x;
    float sl = 0.f, sa = 0.f, st = 0.f;
    for (int r = tid; r < RR; r += 256) {
        sl += g_Tl[base + r] * w1l[r];
        sa += g_Ta[base + r] * w1a[r];
        st += g_Tt[base + r] * w1t[r];
    }
    __shared__ float red[3][8];
    int warp = tid >> 5, lane = tid & 31;
    #pragma unroll
    for (int off = 16; off; off >>= 1) {
        sl += __shfl_xor_sync(0xffffffffu, sl, off);
        sa += __shfl_xor_sync(0xffffffffu, sa, off);
        st += __shfl_xor_sync(0xffffffffu, st, off);
    }
    if (lane == 0) { red[0][warp] = sl; red[1][warp] = sa; red[2][warp] = st; }
    __syncthreads();
    if (tid == 0) {
        float SL = 0.f, SA = 0.f, ST = 0.f;
        #pragma unroll
        for (int w = 0; w < 8; w++) { SL += red[0][w]; SA += red[1][w]; ST += red[2][w]; }
        out[b*LL + l] = SL + b1l[0];
        g_accu1v[b*LL + l] = tanhf(SA + b1a[0]);
        g_term1v[b*LL + l] = tanhf(ST + b1t[0]);
    }
}

// ---------------- final tiny classifier heads --------------------------------
__global__ void final_kernel(const float* __restrict__ Wa2, const float* __restrict__ ba2,
                             const float* __restrict__ Wt2, const float* __restrict__ bt2,
                             float* __restrict__ out)
{
    int t = threadIdx.x;
    if (t < BB*119) {
        int b = t / 119, j = t % 119;
        float s = 0.f;
        for (int l = 0; l < LL; l++) s += g_accu1v[b*LL + l] * Wa2[j*LL + l];
        out[BB*LL + b*119 + j] = s + ba2[j];
    } else if (t < BB*119 + BB*11) {
        int u = t - BB*119;
        int b = u / 11, j = u % 11;
        float s = 0.f;
        for (int l = 0; l < LL; l++) s += g_term1v[b*LL + l] * Wt2[j*LL + l];
        out[BB*LL + BB*119 + b*11 + j] = s + bt2[j];
    }
}

// ---------------- launcher ---------------------------------------------------
extern "C" void kernel_launch(void* const* d_in, const int* in_sizes, int n_in,
                              void* d_out, int out_size)
{
    const float* outp = (const float*)d_in[0];
    const int*   mask = (const int*)  d_in[1];
    const float* laws = (const float*)d_in[2];
    const float* Wq   = (const float*)d_in[3];
    const float* bq   = (const float*)d_in[4];
    const float* Wk   = (const float*)d_in[5];
    const float* bk   = (const float*)d_in[6];
    const float* Wv   = (const float*)d_in[7];
    const float* bv   = (const float*)d_in[8];
    const float* wld  = (const float*)d_in[9];
    const float* bld  = (const float*)d_in[10];
    const float* wl1  = (const float*)d_in[11];
    const float* bl1  = (const float*)d_in[12];
    const float* wad  = (const float*)d_in[13];
    const float* badp = (const float*)d_in[14];
    const float* wa1  = (const float*)d_in[15];
    const float* ba1  = (const float*)d_in[16];
    const float* Wa2  = (const float*)d_in[17];
    const float* ba2  = (const float*)d_in[18];
    const float* wtd  = (const float*)d_in[19];
    const float* btdp = (const float*)d_in[20];
    const float* wt1  = (const float*)d_in[21];
    const float* bt1  = (const float*)d_in[22];
    const float* Wt2  = (const float*)d_in[23];
    const float* bt2  = (const float*)d_in[24];
    float* out = (float*)d_out;

    cudaFuncSetAttribute(attn_kernel, cudaFuncAttributeMaxDynamicSharedMemorySize, SMEM_BYTES);

    // 1) small matvecs: c1 = Wq·bk, vbq = Wk·bq, vX = Wv·w_X_d
    matvec_kernel<<<96, 256>>>(Wq, bk, 0);
    matvec_kernel<<<96, 256>>>(Wk, bq, 1);
    matvec_kernel<<<96, 256>>>(Wv, wld, 2);
    matvec_kernel<<<96, 256>>>(Wv, wad, 3);
    matvec_kernel<<<96, 256>>>(Wv, wtd, 4);

    // 2) Mt = Wq x Wk^T  (768x768, K=768)
    {
        dim3 g(DD/64, DD/64);
        nt_gemm64<<<g, 256>>>(Wq, Wk, DD, DD, 0);
    }
    // 3) fk2' = inv*(output x Mt^T + c1)  (1024x768, K=768)
    {
        dim3 g(DD/64, NCOL/64);
        nt_gemm64<<<g, 256>>>(outp, nullptr, DD, DD, 1);
    }
    // 4) per-column bias + projected V values
    colbias_kernel<<<NCOL, 256>>>(outp, mask, bk, bq, bv, wld, wad, wtd);

    // 5) fused scores-GEMM + online softmax + weighted sums + tanh
    attn_kernel<<<ROWS/TM, 256, SMEM_BYTES>>>(laws, bld, badp, btdp);

    // 6) reduce over r per (b,l)
    head_reduce_kernel<<<BB*LL, 256>>>(wl1, bl1, wa1, ba1, wt1, bt1, out);

    // 7) tiny classifier heads
    final_kernel<<<1, 288>>>(Wa2, ba2, Wt2, bt2, out);
}

// round 6
// speedup vs baseline: 3.8475x; 3.8475x over previous
#include <cuda_runtime.h>
#include <cuda_fp16.h>
#include <math.h>
#include <stdint.h>

// Problem constants
#define LL 103
#define RR 512
#define BB 2
#define SS 512
#define DD 768
#define ROWS (LL*RR)        // 52736
#define NCOL (BB*SS)        // 1024
#define INV_SQRT_D 0.03608439182435161269f

// ---------------- device scratch (static: no allocation allowed) -------------
__device__ float g_Mt[DD*DD];
__device__ float g_c1[DD];
__device__ float g_vbq[DD], g_vlaw[DD], g_vaccu[DD], g_vterm[DD];
__device__ float g_colb[NCOL], g_pvl[NCOL], g_pva[NCOL], g_pvt[NCOL];
__device__ float g_Tl[BB*ROWS], g_Ta[BB*ROWS], g_Tt[BB*ROWS];
__device__ float g_accu1v[BB*LL], g_term1v[BB*LL];
// fp16 operands for the HMMA GEMM
__device__ __half g_lawsF[ROWS*DD];   // 81MB
__device__ __half g_fk2F[NCOL*DD];    // 1.5MB

// ======================= PTX helpers ========================================
__device__ __forceinline__ uint32_t smem_u32(const void* p) {
    uint32_t a;
    asm("{ .reg .u64 t; cvta.to.shared.u64 t, %1; cvt.u32.u64 %0, t; }"
        : "=r"(a) : "l"(p));
    return a;
}
__device__ __forceinline__ void cp16(uint32_t dst, const void* src) {
    asm volatile("cp.async.cg.shared.global [%0], [%1], 16;" :: "r"(dst), "l"(src));
}
#define CP_COMMIT() asm volatile("cp.async.commit_group;" ::: "memory")

#define LDSM4(r0_, r1_, r2_, r3_, addr)                                        \
    asm volatile("ldmatrix.sync.aligned.m8n8.x4.shared.b16 {%0,%1,%2,%3}, [%4];" \
        : "=r"(r0_), "=r"(r1_), "=r"(r2_), "=r"(r3_) : "r"(addr))
#define LDSM2(r0_, r1_, addr)                                                  \
    asm volatile("ldmatrix.sync.aligned.m8n8.x2.shared.b16 {%0,%1}, [%2];"     \
        : "=r"(r0_), "=r"(r1_) : "r"(addr))

__device__ __forceinline__ void mma16816(float* c, const uint32_t* a, const uint32_t* b) {
    asm volatile(
        "mma.sync.aligned.m16n8k16.row.col.f32.f16.f16.f32 "
        "{%0,%1,%2,%3}, {%4,%5,%6,%7}, {%8,%9}, {%0,%1,%2,%3};"
        : "+f"(c[0]), "+f"(c[1]), "+f"(c[2]), "+f"(c[3])
        : "r"(a[0]), "r"(a[1]), "r"(a[2]), "r"(a[3]), "r"(b[0]), "r"(b[1]));
}

// ======================= prep kernels =======================================
__global__ void matvec_kernel(const float* __restrict__ M,
                              const float* __restrict__ v, int which)
{
    int row = blockIdx.x * 8 + (threadIdx.x >> 5);
    int lane = threadIdx.x & 31;
    if (row >= DD) return;
    float s = 0.f;
    for (int k = lane; k < DD; k += 32) s += M[(size_t)row*DD + k] * v[k];
    #pragma unroll
    for (int off = 16; off; off >>= 1) s += __shfl_xor_sync(0xffffffffu, s, off);
    if (lane == 0) {
        if      (which == 0) g_c1[row]    = s;
        else if (which == 1) g_vbq[row]   = s;
        else if (which == 2) g_vlaw[row]  = s;
        else if (which == 3) g_vaccu[row] = s;
        else                 g_vterm[row] = s;
    }
}

// mode 0: C=g_Mt (fp32). mode 1: write g_fk2F (fp16), alpha=inv, bias=g_c1
__global__ __launch_bounds__(256) void nt_gemm64(const float* __restrict__ A,
                                                 const float* __restrict__ Bp,
                                                 int K, int N, int mode)
{
    __shared__ float As2[16*68];
    __shared__ float Bs2[16*68];
    const float* B = (mode == 0) ? Bp : g_Mt;
    const float alpha = (mode == 0) ? 1.0f : INV_SQRT_D;

    int tid = threadIdx.x;
    int tx = tid & 15, ty = tid >> 4;
    int j0 = blockIdx.x * 64, i0 = blockIdx.y * 64;
    float acc[4][4];
    #pragma unroll
    for (int i = 0; i < 4; i++)
        #pragma unroll
        for (int j = 0; j < 4; j++) acc[i][j] = 0.f;

    int row = tid >> 2, q = tid & 3;
    for (int kk = 0; kk < K; kk += 16) {
        __syncthreads();
        float4 va = *reinterpret_cast<const float4*>(&A[(size_t)(i0+row)*K + kk + q*4]);
        As2[(q*4+0)*68+row] = va.x; As2[(q*4+1)*68+row] = va.y;
        As2[(q*4+2)*68+row] = va.z; As2[(q*4+3)*68+row] = va.w;
        float4 vb = *reinterpret_cast<const float4*>(&B[(size_t)(j0+row)*K + kk + q*4]);
        Bs2[(q*4+0)*68+row] = vb.x; Bs2[(q*4+1)*68+row] = vb.y;
        Bs2[(q*4+2)*68+row] = vb.z; Bs2[(q*4+3)*68+row] = vb.w;
        __syncthreads();
        #pragma unroll
        for (int k = 0; k < 16; k++) {
            float4 a = *reinterpret_cast<const float4*>(&As2[k*68 + ty*4]);
            float4 b = *reinterpret_cast<const float4*>(&Bs2[k*68 + tx*4]);
            float av[4] = {a.x, a.y, a.z, a.w};
            float bv[4] = {b.x, b.y, b.z, b.w};
            #pragma unroll
            for (int i = 0; i < 4; i++)
                #pragma unroll
                for (int j = 0; j < 4; j++) acc[i][j] += av[i]*bv[j];
        }
    }
    #pragma unroll
    for (int i = 0; i < 4; i++)
        #pragma unroll
        for (int j = 0; j < 4; j++) {
            int cj = j0 + tx*4 + j;
            size_t idx = (size_t)(i0 + ty*4 + i)*N + cj;
            if (mode == 0) {
                g_Mt[idx] = alpha*acc[i][j];
            } else {
                float val = alpha*(acc[i][j] + g_c1[cj]);
                g_fk2F[idx] = __float2half_rn(val);
            }
        }
}

// fp16 conversion of laws (one float4 per thread)
__global__ void tohalf_laws(const float* __restrict__ src)
{
    size_t i = (size_t)blockIdx.x * 256 + threadIdx.x;
    float4 v = reinterpret_cast<const float4*>(src)[i];
    __half2* d = reinterpret_cast<__half2*>(g_lawsF);
    d[2*i]   = __floats2half2_rn(v.x, v.y);
    d[2*i+1] = __floats2half2_rn(v.z, v.w);
}

__global__ void colbias_kernel(const float* __restrict__ outp,
                               const int*   __restrict__ mask,
                               const float* __restrict__ bk, const float* __restrict__ bq,
                               const float* __restrict__ bv,
                               const float* __restrict__ wl, const float* __restrict__ wa,
                               const float* __restrict__ wt)
{
    int j = blockIdx.x;
    int tid = threadIdx.x;
    float s[8] = {0,0,0,0,0,0,0,0};
    for (int k = tid; k < DD; k += 256) {
        float o = outp[(size_t)j*DD + k];
        s[0] += o * g_vbq[k];
        s[1] += o * g_vlaw[k];
        s[2] += o * g_vaccu[k];
        s[3] += o * g_vterm[k];
        s[4] += bk[k]*bq[k];
        s[5] += bv[k]*wl[k];
        s[6] += bv[k]*wa[k];
        s[7] += bv[k]*wt[k];
    }
    __shared__ float red[8][8];
    int warp = tid >> 5, lane = tid & 31;
    #pragma unroll
    for (int v = 0; v < 8; v++) {
        float x = s[v];
        #pragma unroll
        for (int off = 16; off; off >>= 1) x += __shfl_xor_sync(0xffffffffu, x, off);
        if (lane == 0) red[v][warp] = x;
    }
    __syncthreads();
    if (tid == 0) {
        float t[8];
        #pragma unroll
        for (int v = 0; v < 8; v++) {
            float x = 0.f;
            #pragma unroll
            for (int w = 0; w < 8; w++) x += red[v][w];
            t[v] = x;
        }
        g_colb[j] = (t[0] + t[4]) * INV_SQRT_D + (1.0f - (float)mask[j]) * (-10000.0f);
        g_pvl[j] = t[1] + t[5];
        g_pva[j] = t[2] + t[6];
        g_pvt[j] = t[3] + t[7];
    }
}

// ======================= main HMMA attention kernel ==========================
// SMEM: 3 stages x (A 128x32 fp16 pitch80 = 10240B | B same) = 61440
//       pv tables 16384, merge 2560
#define ST_BYTES 20480
#define SM_PV    (3*ST_BYTES)          // 61440
#define SM_MERGE (SM_PV + 16384)       // 77824
#define SMEM3    (SM_MERGE + 2560 + 64)

__device__ __forceinline__ void load3(int it, int r0, uint32_t sb)
{
    int chunk = it / 24, kt = it - chunk*24;
    int j0 = chunk * 128, kc = kt * 32;
    uint32_t st = sb + (uint32_t)(it % 3) * ST_BYTES;
    int t = threadIdx.x;
    #pragma unroll
    for (int p = 0; p < 2; p++) {
        int id = p*256 + t;
        int row = id >> 2, ch = id & 3;
        const char* src = (const char*)(g_lawsF + (size_t)(r0+row)*DD + kc) + ch*16;
        cp16(st + (uint32_t)(row*80 + ch*16), src);
    }
    #pragma unroll
    for (int p = 0; p < 2; p++) {
        int id = p*256 + t;
        int row = id >> 2, ch = id & 3;
        const char* src = (const char*)(g_fk2F + (size_t)(j0+row)*DD + kc) + ch*16;
        cp16(st + 10240u + (uint32_t)(row*80 + ch*16), src);
    }
}

__global__ __launch_bounds__(256) void attn3_kernel(
    const float* __restrict__ bld, const float* __restrict__ bad,
    const float* __restrict__ btd)
{
    extern __shared__ char smem[];
    uint32_t sb = smem_u32(smem);
    float* pv    = reinterpret_cast<float*>(smem + SM_PV);
    float* merge = reinterpret_cast<float*>(smem + SM_MERGE);
    const int tid = threadIdx.x;
    const int lane = tid & 31, wid = tid >> 5;
    const int wm = wid & 3, wn = wid >> 2;
    const int r0 = blockIdx.x * 128;

    for (int i = tid; i < 1024; i += 256) {
        pv[i]        = g_colb[i];
        pv[1024 + i] = g_pvl[i];
        pv[2048 + i] = g_pva[i];
        pv[3072 + i] = g_pvt[i];
    }

    // prologue: stages 0 and 1
    load3(0, r0, sb); CP_COMMIT();
    load3(1, r0, sb); CP_COMMIT();

    const float bias_l = *bld, bias_a = *bad, bias_t = *btd;

    float acc[2][8][4];
    float run_m[2][2], run_z[2][2], run_w0[2][2], run_w1[2][2], run_w2[2][2];
    #pragma unroll
    for (int mt = 0; mt < 2; mt++)
        #pragma unroll
        for (int h = 0; h < 2; h++) {
            run_m[mt][h] = -1e30f; run_z[mt][h] = 0.f;
            run_w0[mt][h] = 0.f; run_w1[mt][h] = 0.f; run_w2[mt][h] = 0.f;
        }

    for (int it = 0; it < 192; it++) {
        const int chunk = it / 24;
        const int kt = it - chunk*24;
        if (kt == 0) {
            #pragma unroll
            for (int mt = 0; mt < 2; mt++)
                #pragma unroll
                for (int nt = 0; nt < 8; nt++)
                    #pragma unroll
                    for (int k = 0; k < 4; k++) acc[mt][nt][k] = 0.f;
        }

        if (it < 191) asm volatile("cp.async.wait_group 1;" ::: "memory");
        else          asm volatile("cp.async.wait_group 0;" ::: "memory");
        __syncthreads();

        if (it + 2 < 192) { load3(it + 2, r0, sb); CP_COMMIT(); }

        // compute this stage
        const uint32_t stb = sb + (uint32_t)(it % 3) * ST_BYTES;
        #pragma unroll
        for (int ks = 0; ks < 2; ks++) {
            uint32_t afr[2][4];
            uint32_t bfr[8][2];
            #pragma unroll
            for (int mt = 0; mt < 2; mt++) {
                uint32_t ad = stb + (uint32_t)((wm*32 + mt*16 + (lane & 15))*80
                                               + ks*32 + (lane >> 4)*16);
                LDSM4(afr[mt][0], afr[mt][1], afr[mt][2], afr[mt][3], ad);
            }
            #pragma unroll
            for (int nt = 0; nt < 8; nt++) {
                uint32_t bd = stb + 10240u + (uint32_t)((wn*64 + nt*8 + (lane & 7))*80
                                                        + ks*32 + ((lane >> 3) & 1)*16);
                LDSM2(bfr[nt][0], bfr[nt][1], bd);
            }
            #pragma unroll
            for (int mt = 0; mt < 2; mt++)
                #pragma unroll
                for (int nt = 0; nt < 8; nt++)
                    mma16816(acc[mt][nt], afr[mt], bfr[nt]);
        }

        if (kt == 23) {
            const int cc = chunk;
            const int jb = cc*128 + wn*64 + 2*(lane & 3);
            float gm[2][2], gz[2][2], g0[2][2], g1[2][2], g2[2][2];
            #pragma unroll
            for (int mt = 0; mt < 2; mt++) {
                #pragma unroll
                for (int h = 0; h < 2; h++) {
                    float mx = -1e30f;
                    float vv[16];
                    #pragma unroll
                    for (int nt = 0; nt < 8; nt++) {
                        float v0 = acc[mt][nt][2*h]   + pv[jb + nt*8];
                        float v1 = acc[mt][nt][2*h+1] + pv[jb + nt*8 + 1];
                        vv[2*nt] = v0; vv[2*nt+1] = v1;
                        mx = fmaxf(mx, fmaxf(v0, v1));
                    }
                    mx = fmaxf(mx, __shfl_xor_sync(0xffffffffu, mx, 1));
                    mx = fmaxf(mx, __shfl_xor_sync(0xffffffffu, mx, 2));
                    float z = 0.f, w0 = 0.f, w1 = 0.f, w2 = 0.f;
                    #pragma unroll
                    for (int nt = 0; nt < 8; nt++) {
                        int j = jb + nt*8;
                        float e0 = __expf(vv[2*nt]   - mx);
                        float e1 = __expf(vv[2*nt+1] - mx);
                        z  += e0 + e1;
                        w0 += e0*pv[1024+j] + e1*pv[1025+j];
                        w1 += e0*pv[2048+j] + e1*pv[2049+j];
                        w2 += e0*pv[3072+j] + e1*pv[3073+j];
                    }
                    #pragma unroll
                    for (int off = 1; off < 4; off <<= 1) {
                        z  += __shfl_xor_sync(0xffffffffu, z,  off);
                        w0 += __shfl_xor_sync(0xffffffffu, w0, off);
                        w1 += __shfl_xor_sync(0xffffffffu, w1, off);
                        w2 += __shfl_xor_sync(0xffffffffu, w2, off);
                    }
                    gm[mt][h] = mx; gz[mt][h] = z;
                    g0[mt][h] = w0; g1[mt][h] = w1; g2[mt][h] = w2;
                }
            }
            if (wn == 1 && (lane & 3) == 0) {
                #pragma unroll
                for (int mt = 0; mt < 2; mt++)
                    #pragma unroll
                    for (int h = 0; h < 2; h++) {
                        int row = wm*32 + mt*16 + (lane >> 2) + 8*h;
                        merge[row*5+0] = gm[mt][h]; merge[row*5+1] = gz[mt][h];
                        merge[row*5+2] = g0[mt][h]; merge[row*5+3] = g1[mt][h];
                        merge[row*5+4] = g2[mt][h];
                    }
            }
            __syncthreads();
            if (wn == 0 && (lane & 3) == 0) {
                #pragma unroll
                for (int mt = 0; mt < 2; mt++)
                    #pragma unroll
                    for (int h = 0; h < 2; h++) {
                        int row = wm*32 + mt*16 + (lane >> 2) + 8*h;
                        float m1 = merge[row*5+0], z1 = merge[row*5+1];
                        float a1 = merge[row*5+2], b1 = merge[row*5+3], c1v = merge[row*5+4];
                        float nm = fmaxf(gm[mt][h], m1);
                        float s0 = __expf(gm[mt][h] - nm), s1 = __expf(m1 - nm);
                        float cz  = gz[mt][h]*s0 + z1*s1;
                        float cw0 = g0[mt][h]*s0 + a1*s1;
                        float cw1 = g1[mt][h]*s0 + b1*s1;
                        float cw2 = g2[mt][h]*s0 + c1v*s1;
                        float nm2 = fmaxf(run_m[mt][h], nm);
                        float sa  = __expf(run_m[mt][h] - nm2), sb2 = __expf(nm - nm2);
                        run_z[mt][h]  = run_z[mt][h]*sa  + cz*sb2;
                        run_w0[mt][h] = run_w0[mt][h]*sa + cw0*sb2;
                        run_w1[mt][h] = run_w1[mt][h]*sa + cw1*sb2;
                        run_w2[mt][h] = run_w2[mt][h]*sa + cw2*sb2;
                        run_m[mt][h]  = nm2;
                        if ((cc & 3) == 3) {
                            int b = cc >> 2;
                            int rg = r0 + row;
                            float inv = 1.0f / run_z[mt][h];
                            g_Tl[b*ROWS + rg] = tanhf(run_w0[mt][h]*inv + bias_l);
                            g_Ta[b*ROWS + rg] = tanhf(run_w1[mt][h]*inv + bias_a);
                            g_Tt[b*ROWS + rg] = tanhf(run_w2[mt][h]*inv + bias_t);
                            run_m[mt][h] = -1e30f; run_z[mt][h] = 0.f;
                            run_w0[mt][h] = 0.f; run_w1[mt][h] = 0.f; run_w2[mt][h] = 0.f;
                        }
                    }
            }
        }
    }
}

// ---------------- reduce over r (512) per (b,l) ------------------------------
__global__ void head_reduce_kernel(const float* __restrict__ w1l, const float* __restrict__ b1l,
                                   const float* __restrict__ w1a, const float* __restrict__ b1a,
                                   const float* __restrict__ w1t, const float* __restrict__ b1t,
                                   float* __restrict__ out)
{
    int bl = blockIdx.x;
    int b = bl / LL, l = bl % LL;
    size_t base = (size_t)b*ROWS + (size_t)l*RR;
    int tid = threadIdx.x;
    float sl = 0.f, sa = 0.f, st = 0.f;
    for (int r = tid; r < RR; r += 256) {
        sl += g_Tl[base + r] * w1l[r];
        sa += g_Ta[base + r] * w1a[r];
        st += g_Tt[base + r] * w1t[r];
    }
    __shared__ float red[3][8];
    int warp = tid >> 5, lane = tid & 31;
    #pragma unroll
    for (int off = 16; off; off >>= 1) {
        sl += __shfl_xor_sync(0xffffffffu, sl, off);
        sa += __shfl_xor_sync(0xffffffffu, sa, off);
        st += __shfl_xor_sync(0xffffffffu, st, off);
    }
    if (lane == 0) { red[0][warp] = sl; red[1][warp] = sa; red[2][warp] = st; }
    __syncthreads();
    if (tid == 0) {
        float SL = 0.f, SA = 0.f, ST = 0.f;
        #pragma unroll
        for (int w = 0; w < 8; w++) { SL += red[0][w]; SA += red[1][w]; ST += red[2][w]; }
        out[b*LL + l] = SL + b1l[0];
        g_accu1v[b*LL + l] = tanhf(SA + b1a[0]);
        g_term1v[b*LL + l] = tanhf(ST + b1t[0]);
    }
}

// ---------------- final tiny classifier heads --------------------------------
__global__ void final_kernel(const float* __restrict__ Wa2, const float* __restrict__ ba2,
                             const float* __restrict__ Wt2, const float* __restrict__ bt2,
                             float* __restrict__ out)
{
    int t = threadIdx.x;
    if (t < BB*119) {
        int b = t / 119, j = t % 119;
        float s = 0.f;
        for (int l = 0; l < LL; l++) s += g_accu1v[b*LL + l] * Wa2[j*LL + l];
        out[BB*LL + b*119 + j] = s + ba2[j];
    } else if (t < BB*119 + BB*11) {
        int u = t - BB*119;
        int b = u / 11, j = u % 11;
        float s = 0.f;
        for (int l = 0; l < LL; l++) s += g_term1v[b*LL + l] * Wt2[j*LL + l];
        out[BB*LL + BB*119 + b*11 + j] = s + bt2[j];
    }
}

// ---------------- launcher ---------------------------------------------------
extern "C" void kernel_launch(void* const* d_in, const int* in_sizes, int n_in,
                              void* d_out, int out_size)
{
    const float* outp = (const float*)d_in[0];
    const int*   mask = (const int*)  d_in[1];
    const float* laws = (const float*)d_in[2];
    const float* Wq   = (const float*)d_in[3];
    const float* bq   = (const float*)d_in[4];
    const float* Wk   = (const float*)d_in[5];
    const float* bk   = (const float*)d_in[6];
    const float* Wv   = (const float*)d_in[7];
    const float* bv   = (const float*)d_in[8];
    const float* wld  = (const float*)d_in[9];
    const float* bld  = (const float*)d_in[10];
    const float* wl1  = (const float*)d_in[11];
    const float* bl1  = (const float*)d_in[12];
    const float* wad  = (const float*)d_in[13];
    const float* badp = (const float*)d_in[14];
    const float* wa1  = (const float*)d_in[15];
    const float* ba1  = (const float*)d_in[16];
    const float* Wa2  = (const float*)d_in[17];
    const float* ba2  = (const float*)d_in[18];
    const float* wtd  = (const float*)d_in[19];
    const float* btdp = (const float*)d_in[20];
    const float* wt1  = (const float*)d_in[21];
    const float* bt1  = (const float*)d_in[22];
    const float* Wt2  = (const float*)d_in[23];
    const float* bt2  = (const float*)d_in[24];
    float* out = (float*)d_out;

    cudaFuncSetAttribute(attn3_kernel, cudaFuncAttributeMaxDynamicSharedMemorySize, SMEM3);

    // 1) small matvecs
    matvec_kernel<<<96, 256>>>(Wq, bk, 0);
    matvec_kernel<<<96, 256>>>(Wk, bq, 1);
    matvec_kernel<<<96, 256>>>(Wv, wld, 2);
    matvec_kernel<<<96, 256>>>(Wv, wad, 3);
    matvec_kernel<<<96, 256>>>(Wv, wtd, 4);

    // 2) Mt = Wq x Wk^T
    { dim3 g(DD/64, DD/64); nt_gemm64<<<g, 256>>>(Wq, Wk, DD, DD, 0); }
    // 3) fk2 = inv*(output x Mt^T + c1), written as fp16
    { dim3 g(DD/64, NCOL/64); nt_gemm64<<<g, 256>>>(outp, nullptr, DD, DD, 1); }
    // 4) column bias + projected V values
    colbias_kernel<<<NCOL, 256>>>(outp, mask, bk, bq, bv, wld, wad, wtd);
    // 5) fp16 conversion of laws
    tohalf_laws<<<(ROWS*DD/4)/256, 256>>>(laws);
    // 6) HMMA fused scores GEMM + online softmax + weighted sums + tanh
    attn3_kernel<<<ROWS/128, 256, SMEM3>>>(bld, badp, btdp);
    // 7) reduce over r per (b,l)
    head_reduce_kernel<<<BB*LL, 256>>>(wl1, bl1, wa1, ba1, wt1, bt1, out);
    // 8) tiny classifier heads
    final_kernel<<<1, 288>>>(Wa2, ba2, Wt2, bt2, out);
}

// round 7
// speedup vs baseline: 5.0373x; 1.3092x over previous
#include <cuda_runtime.h>
#include <cuda_fp16.h>
#include <math.h>
#include <stdint.h>

// Problem constants
#define LL 103
#define RR 512
#define BB 2
#define SS 512
#define DD 768
#define ROWS (LL*RR)        // 52736
#define NCOL (BB*SS)        // 1024
#define INV_SQRT_D 0.03608439182435161269f

// ---------------- device scratch (static: no allocation allowed) -------------
__device__ float g_Mt[DD*DD];
__device__ float g_c1[DD];
__device__ float g_vbq[DD], g_vlaw[DD], g_vaccu[DD], g_vterm[DD];
__device__ float g_colb[NCOL], g_pvl[NCOL], g_pva[NCOL], g_pvt[NCOL];
__device__ float g_Tl[BB*ROWS], g_Ta[BB*ROWS], g_Tt[BB*ROWS];
__device__ float g_accu1v[BB*LL], g_term1v[BB*LL];
__device__ __half g_lawsF[ROWS*DD];   // 81MB
__device__ __half g_fk2F[NCOL*DD];    // 1.5MB

// ======================= PTX helpers ========================================
__device__ __forceinline__ uint32_t smem_u32(const void* p) {
    uint32_t a;
    asm("{ .reg .u64 t; cvta.to.shared.u64 t, %1; cvt.u32.u64 %0, t; }"
        : "=r"(a) : "l"(p));
    return a;
}
__device__ __forceinline__ void cp16(uint32_t dst, const void* src) {
    asm volatile("cp.async.cg.shared.global [%0], [%1], 16;" :: "r"(dst), "l"(src));
}
#define CP_COMMIT() asm volatile("cp.async.commit_group;" ::: "memory")

#define LDSM4(r0_, r1_, r2_, r3_, addr)                                        \
    asm volatile("ldmatrix.sync.aligned.m8n8.x4.shared.b16 {%0,%1,%2,%3}, [%4];" \
        : "=r"(r0_), "=r"(r1_), "=r"(r2_), "=r"(r3_) : "r"(addr))

__device__ __forceinline__ void mma16816(float* c, const uint32_t* a,
                                         uint32_t b0, uint32_t b1) {
    asm volatile(
        "mma.sync.aligned.m16n8k16.row.col.f32.f16.f16.f32 "
        "{%0,%1,%2,%3}, {%4,%5,%6,%7}, {%8,%9}, {%0,%1,%2,%3};"
        : "+f"(c[0]), "+f"(c[1]), "+f"(c[2]), "+f"(c[3])
        : "r"(a[0]), "r"(a[1]), "r"(a[2]), "r"(a[3]), "r"(b0), "r"(b1));
}

// ======================= prep kernels =======================================
// fused: all 5 matvecs in one launch.  g = global warp row over 5*768
__global__ void matvec5_kernel(const float* __restrict__ Wq,
                               const float* __restrict__ Wk,
                               const float* __restrict__ Wv,
                               const float* __restrict__ bk,
                               const float* __restrict__ bq,
                               const float* __restrict__ wld,
                               const float* __restrict__ wad,
                               const float* __restrict__ wtd)
{
    int g = blockIdx.x * 8 + (threadIdx.x >> 5);
    int lane = threadIdx.x & 31;
    if (g >= 5*DD) return;
    int which = g / DD, row = g - which*DD;
    const float* M = (which == 0) ? Wq : (which == 1) ? Wk : Wv;
    const float* v = (which == 0) ? bk : (which == 1) ? bq :
                     (which == 2) ? wld : (which == 3) ? wad : wtd;
    float s = 0.f;
    for (int k = lane; k < DD; k += 32) s += M[(size_t)row*DD + k] * v[k];
    #pragma unroll
    for (int off = 16; off; off >>= 1) s += __shfl_xor_sync(0xffffffffu, s, off);
    if (lane == 0) {
        if      (which == 0) g_c1[row]    = s;
        else if (which == 1) g_vbq[row]   = s;
        else if (which == 2) g_vlaw[row]  = s;
        else if (which == 3) g_vaccu[row] = s;
        else                 g_vterm[row] = s;
    }
}

// mode 0: C=g_Mt (fp32). mode 1: write g_fk2F (fp16), alpha=inv, bias=g_c1
__global__ __launch_bounds__(256) void nt_gemm64(const float* __restrict__ A,
                                                 const float* __restrict__ Bp,
                                                 int K, int N, int mode)
{
    __shared__ float As2[16*68];
    __shared__ float Bs2[16*68];
    const float* B = (mode == 0) ? Bp : g_Mt;
    const float alpha = (mode == 0) ? 1.0f : INV_SQRT_D;

    int tid = threadIdx.x;
    int tx = tid & 15, ty = tid >> 4;
    int j0 = blockIdx.x * 64, i0 = blockIdx.y * 64;
    float acc[4][4];
    #pragma unroll
    for (int i = 0; i < 4; i++)
        #pragma unroll
        for (int j = 0; j < 4; j++) acc[i][j] = 0.f;

    int row = tid >> 2, q = tid & 3;
    for (int kk = 0; kk < K; kk += 16) {
        __syncthreads();
        float4 va = *reinterpret_cast<const float4*>(&A[(size_t)(i0+row)*K + kk + q*4]);
        As2[(q*4+0)*68+row] = va.x; As2[(q*4+1)*68+row] = va.y;
        As2[(q*4+2)*68+row] = va.z; As2[(q*4+3)*68+row] = va.w;
        float4 vb = *reinterpret_cast<const float4*>(&B[(size_t)(j0+row)*K + kk + q*4]);
        Bs2[(q*4+0)*68+row] = vb.x; Bs2[(q*4+1)*68+row] = vb.y;
        Bs2[(q*4+2)*68+row] = vb.z; Bs2[(q*4+3)*68+row] = vb.w;
        __syncthreads();
        #pragma unroll
        for (int k = 0; k < 16; k++) {
            float4 a = *reinterpret_cast<const float4*>(&As2[k*68 + ty*4]);
            float4 b = *reinterpret_cast<const float4*>(&Bs2[k*68 + tx*4]);
            float av[4] = {a.x, a.y, a.z, a.w};
            float bv[4] = {b.x, b.y, b.z, b.w};
            #pragma unroll
            for (int i = 0; i < 4; i++)
                #pragma unroll
                for (int j = 0; j < 4; j++) acc[i][j] += av[i]*bv[j];
        }
    }
    #pragma unroll
    for (int i = 0; i < 4; i++)
        #pragma unroll
        for (int j = 0; j < 4; j++) {
            int cj = j0 + tx*4 + j;
            size_t idx = (size_t)(i0 + ty*4 + i)*N + cj;
            if (mode == 0) {
                g_Mt[idx] = alpha*acc[i][j];
            } else {
                float val = alpha*(acc[i][j] + g_c1[cj]);
                g_fk2F[idx] = __float2half_rn(val);
            }
        }
}

__global__ void tohalf_laws(const float* __restrict__ src)
{
    size_t i = (size_t)blockIdx.x * 256 + threadIdx.x;
    float4 v = reinterpret_cast<const float4*>(src)[i];
    __half2* d = reinterpret_cast<__half2*>(g_lawsF);
    d[2*i]   = __floats2half2_rn(v.x, v.y);
    d[2*i+1] = __floats2half2_rn(v.z, v.w);
}

__global__ void colbias_kernel(const float* __restrict__ outp,
                               const int*   __restrict__ mask,
                               const float* __restrict__ bk, const float* __restrict__ bq,
                               const float* __restrict__ bv,
                               const float* __restrict__ wl, const float* __restrict__ wa,
                               const float* __restrict__ wt)
{
    int j = blockIdx.x;
    int tid = threadIdx.x;
    float s[8] = {0,0,0,0,0,0,0,0};
    for (int k = tid; k < DD; k += 256) {
        float o = outp[(size_t)j*DD + k];
        s[0] += o * g_vbq[k];
        s[1] += o * g_vlaw[k];
        s[2] += o * g_vaccu[k];
        s[3] += o * g_vterm[k];
        s[4] += bk[k]*bq[k];
        s[5] += bv[k]*wl[k];
        s[6] += bv[k]*wa[k];
        s[7] += bv[k]*wt[k];
    }
    __shared__ float red[8][8];
    int warp = tid >> 5, lane = tid & 31;
    #pragma unroll
    for (int v = 0; v < 8; v++) {
        float x = s[v];
        #pragma unroll
        for (int off = 16; off; off >>= 1) x += __shfl_xor_sync(0xffffffffu, x, off);
        if (lane == 0) red[v][warp] = x;
    }
    __syncthreads();
    if (tid == 0) {
        float t[8];
        #pragma unroll
        for (int v = 0; v < 8; v++) {
            float x = 0.f;
            #pragma unroll
            for (int w = 0; w < 8; w++) x += red[v][w];
            t[v] = x;
        }
        g_colb[j] = (t[0] + t[4]) * INV_SQRT_D + (1.0f - (float)mask[j]) * (-10000.0f);
        g_pvl[j] = t[1] + t[5];
        g_pva[j] = t[2] + t[6];
        g_pvt[j] = t[3] + t[7];
    }
}

// ======================= main HMMA attention kernel ==========================
// CTA: M=128 rows, chunkN=256 (4 chunks), warp grid 2m x 4n, warp tile 64x64.
// K-stage 64, 3-stage cp.async pipeline, 48 iterations, 1 sync/iter.
#define APITCH4 144
#define A_ST4   (128*APITCH4)          // 18432
#define B_ST4   (256*APITCH4)          // 36864
#define STG4    (A_ST4 + B_ST4)        // 55296
#define SM_PV4  (3*STG4)               // 165888
#define SM_MRG4 (SM_PV4 + 16384)       // 182272
#define SMEM4   (SM_MRG4 + 8192)       // 190464

__device__ __forceinline__ void load4(int it, int r0, uint32_t sb)
{
    const int chunk = it / 12, kt = it - chunk*12;
    const int j0 = chunk * 256, kc = kt * 64;
    const uint32_t st = sb + (uint32_t)(it % 3) * STG4;
    const int tid = threadIdx.x;
    #pragma unroll
    for (int p = 0; p < 4; p++) {       // A: 128 rows x 8 segs of 16B
        int idx = p*256 + tid;
        int row = idx >> 3, seg = idx & 7;
        const char* src = (const char*)(g_lawsF + (size_t)(r0+row)*DD + kc) + seg*16;
        cp16(st + (uint32_t)(row*APITCH4 + seg*16), src);
    }
    #pragma unroll
    for (int p = 0; p < 8; p++) {       // B: 256 rows x 8 segs
        int idx = p*256 + tid;
        int row = idx >> 3, seg = idx & 7;
        const char* src = (const char*)(g_fk2F + (size_t)(j0+row)*DD + kc) + seg*16;
        cp16(st + A_ST4 + (uint32_t)(row*APITCH4 + seg*16), src);
    }
}

__global__ __launch_bounds__(256, 1) void attn4_kernel(
    const float* __restrict__ bld, const float* __restrict__ bad,
    const float* __restrict__ btd)
{
    extern __shared__ char smem[];
    uint32_t sb = smem_u32(smem);
    float* pvc = reinterpret_cast<float*>(smem + SM_PV4);
    float* mrg = reinterpret_cast<float*>(smem + SM_MRG4);
    const int tid = threadIdx.x;
    const int lane = tid & 31, wid = tid >> 5;
    const int wm = wid & 1, wn = wid >> 1;    // 2 m-warps x 4 n-warps
    const int r0 = blockIdx.x * 128;

    for (int i = tid; i < 1024; i += 256) {
        pvc[i]        = g_colb[i];
        pvc[1024 + i] = g_pvl[i];
        pvc[2048 + i] = g_pva[i];
        pvc[3072 + i] = g_pvt[i];
    }

    load4(0, r0, sb); CP_COMMIT();
    load4(1, r0, sb); CP_COMMIT();

    const float bias_l = *bld, bias_a = *bad, bias_t = *btd;

    float acc[4][8][4];
    float st_z[8], st_w0[8], st_w1[8], st_w2[8];
    #pragma unroll
    for (int e = 0; e < 8; e++) { st_z[e]=0.f; st_w0[e]=0.f; st_w1[e]=0.f; st_w2[e]=0.f; }

    // A frag row base per mt; B frag row base per p (computed once)
    const int arow = wm*64 + (lane & 15);
    const int brow = wn*64 + (lane & 7) + ((lane >> 4) << 3);
    const int akb  = (lane >> 4) * 16;
    const int bkb  = ((lane >> 3) & 1) * 16;

    for (int it = 0; it < 48; it++) {
        const int chunk = it / 12;
        const int kt = it - chunk*12;
        if (kt == 0) {
            #pragma unroll
            for (int mt = 0; mt < 4; mt++)
                #pragma unroll
                for (int nt = 0; nt < 8; nt++)
                    #pragma unroll
                    for (int k = 0; k < 4; k++) acc[mt][nt][k] = 0.f;
        }

        if (it == 47) asm volatile("cp.async.wait_group 0;" ::: "memory");
        else          asm volatile("cp.async.wait_group 1;" ::: "memory");
        __syncthreads();

        if (it + 2 < 48) { load4(it + 2, r0, sb); CP_COMMIT(); }

        const uint32_t st = sb + (uint32_t)(it % 3) * STG4;
        #pragma unroll
        for (int ks = 0; ks < 4; ks++) {
            uint32_t af[4][4];
            uint32_t bf[4][4];
            #pragma unroll
            for (int mt = 0; mt < 4; mt++) {
                uint32_t ad = st + (uint32_t)((arow + mt*16)*APITCH4 + ks*32 + akb);
                LDSM4(af[mt][0], af[mt][1], af[mt][2], af[mt][3], ad);
            }
            #pragma unroll
            for (int p = 0; p < 4; p++) {
                uint32_t bd = st + A_ST4 + (uint32_t)((brow + p*16)*APITCH4 + ks*32 + bkb);
                LDSM4(bf[p][0], bf[p][1], bf[p][2], bf[p][3], bd);
            }
            #pragma unroll
            for (int mt = 0; mt < 4; mt++)
                #pragma unroll
                for (int nt = 0; nt < 8; nt++)
                    mma16816(acc[mt][nt], af[mt], bf[nt>>1][(nt&1)*2], bf[nt>>1][(nt&1)*2+1]);
        }

        if (kt == 11) {
            // per-chunk epilogue: register-only exp accumulation (no max needed:
            // logits are O(1); masked cols carry -10000 -> exp underflows to 0)
            const int jb = chunk*256 + wn*64 + 2*(lane & 3);
            #pragma unroll
            for (int mt = 0; mt < 4; mt++) {
                #pragma unroll
                for (int h = 0; h < 2; h++) {
                    const int e = mt*2 + h;
                    float z = 0.f, w0 = 0.f, w1 = 0.f, w2 = 0.f;
                    #pragma unroll
                    for (int nt = 0; nt < 8; nt++) {
                        int j = jb + nt*8;
                        float e0 = __expf(acc[mt][nt][2*h]   + pvc[j]);
                        float e1 = __expf(acc[mt][nt][2*h+1] + pvc[j+1]);
                        z  += e0 + e1;
                        w0 += e0*pvc[1024+j] + e1*pvc[1025+j];
                        w1 += e0*pvc[2048+j] + e1*pvc[2049+j];
                        w2 += e0*pvc[3072+j] + e1*pvc[3073+j];
                    }
                    st_z[e] += z; st_w0[e] += w0; st_w1[e] += w1; st_w2[e] += w2;
                }
            }
            if (chunk & 1) {
                // batch boundary: merge across lane quads, then across 4 n-warps
                #pragma unroll
                for (int e = 0; e < 8; e++) {
                    #pragma unroll
                    for (int off = 1; off < 4; off <<= 1) {
                        st_z[e]  += __shfl_xor_sync(0xffffffffu, st_z[e],  off);
                        st_w0[e] += __shfl_xor_sync(0xffffffffu, st_w0[e], off);
                        st_w1[e] += __shfl_xor_sync(0xffffffffu, st_w1[e], off);
                        st_w2[e] += __shfl_xor_sync(0xffffffffu, st_w2[e], off);
                    }
                }
                if ((lane & 3) == 0) {
                    #pragma unroll
                    for (int mt = 0; mt < 4; mt++)
                        #pragma unroll
                        for (int h = 0; h < 2; h++) {
                            const int e = mt*2 + h;
                            int row = wm*64 + mt*16 + (lane >> 2) + 8*h;
                            float* m = &mrg[row*16 + wn*4];
                            m[0] = st_z[e]; m[1] = st_w0[e]; m[2] = st_w1[e]; m[3] = st_w2[e];
                        }
                }
                __syncthreads();
                if (tid < 128) {
                    int row = tid;
                    float z = 0.f, w0 = 0.f, w1 = 0.f, w2 = 0.f;
                    #pragma unroll
                    for (int w = 0; w < 4; w++) {
                        const float* m = &mrg[row*16 + w*4];
                        z += m[0]; w0 += m[1]; w1 += m[2]; w2 += m[3];
                    }
                    int b = chunk >> 1;
                    int rg = r0 + row;
                    float inv = 1.0f / z;
                    g_Tl[b*ROWS + rg] = tanhf(w0*inv + bias_l);
                    g_Ta[b*ROWS + rg] = tanhf(w1*inv + bias_a);
                    g_Tt[b*ROWS + rg] = tanhf(w2*inv + bias_t);
                }
                #pragma unroll
                for (int e = 0; e < 8; e++) {
                    st_z[e]=0.f; st_w0[e]=0.f; st_w1[e]=0.f; st_w2[e]=0.f;
                }
            }
        }
    }
}

// ---------------- reduce over r (512) per (b,l) ------------------------------
__global__ void head_reduce_kernel(const float* __restrict__ w1l, const float* __restrict__ b1l,
                                   const float* __restrict__ w1a, const float* __restrict__ b1a,
                                   const float* __restrict__ w1t, const float* __restrict__ b1t,
                                   float* __restrict__ out)
{
    int bl = blockIdx.x;
    int b = bl / LL, l = bl % LL;
    size_t base = (size_t)b*ROWS + (size_t)l*RR;
    int tid = threadIdx.x;
    float sl = 0.f, sa = 0.f, st = 0.f;
    for (int r = tid; r < RR; r += 256) {
        sl += g_Tl[base + r] * w1l[r];
        sa += g_Ta[base + r] * w1a[r];
        st += g_Tt[base + r] * w1t[r];
    }
    __shared__ float red[3][8];
    int warp = tid >> 5, lane = tid & 31;
    #pragma unroll
    for (int off = 16; off; off >>= 1) {
        sl += __shfl_xor_sync(0xffffffffu, sl, off);
        sa += __shfl_xor_sync(0xffffffffu, sa, off);
        st += __shfl_xor_sync(0xffffffffu, st, off);
    }
    if (lane == 0) { red[0][warp] = sl; red[1][warp] = sa; red[2][warp] = st; }
    __syncthreads();
    if (tid == 0) {
        float SL = 0.f, SA = 0.f, ST = 0.f;
        #pragma unroll
        for (int w = 0; w < 8; w++) { SL += red[0][w]; SA += red[1][w]; ST += red[2][w]; }
        out[b*LL + l] = SL + b1l[0];
        g_accu1v[b*LL + l] = tanhf(SA + b1a[0]);
        g_term1v[b*LL + l] = tanhf(ST + b1t[0]);
    }
}

// ---------------- final tiny classifier heads --------------------------------
__global__ void final_kernel(const float* __restrict__ Wa2, const float* __restrict__ ba2,
                             const float* __restrict__ Wt2, const float* __restrict__ bt2,
                             float* __restrict__ out)
{
    int t = threadIdx.x;
    if (t < BB*119) {
        int b = t / 119, j = t % 119;
        float s = 0.f;
        for (int l = 0; l < LL; l++) s += g_accu1v[b*LL + l] * Wa2[j*LL + l];
        out[BB*LL + b*119 + j] = s + ba2[j];
    } else if (t < BB*119 + BB*11) {
        int u = t - BB*119;
        int b = u / 11, j = u % 11;
        float s = 0.f;
        for (int l = 0; l < LL; l++) s += g_term1v[b*LL + l] * Wt2[j*LL + l];
        out[BB*LL + BB*119 + b*11 + j] = s + bt2[j];
    }
}

// ---------------- launcher ---------------------------------------------------
extern "C" void kernel_launch(void* const* d_in, const int* in_sizes, int n_in,
                              void* d_out, int out_size)
{
    const float* outp = (const float*)d_in[0];
    const int*   mask = (const int*)  d_in[1];
    const float* laws = (const float*)d_in[2];
    const float* Wq   = (const float*)d_in[3];
    const float* bq   = (const float*)d_in[4];
    const float* Wk   = (const float*)d_in[5];
    const float* bk   = (const float*)d_in[6];
    const float* Wv   = (const float*)d_in[7];
    const float* bv   = (const float*)d_in[8];
    const float* wld  = (const float*)d_in[9];
    const float* bld  = (const float*)d_in[10];
    const float* wl1  = (const float*)d_in[11];
    const float* bl1  = (const float*)d_in[12];
    const float* wad  = (const float*)d_in[13];
    const float* badp = (const float*)d_in[14];
    const float* wa1  = (const float*)d_in[15];
    const float* ba1  = (const float*)d_in[16];
    const float* Wa2  = (const float*)d_in[17];
    const float* ba2  = (const float*)d_in[18];
    const float* wtd  = (const float*)d_in[19];
    const float* btdp = (const float*)d_in[20];
    const float* wt1  = (const float*)d_in[21];
    const float* bt1  = (const float*)d_in[22];
    const float* Wt2  = (const float*)d_in[23];
    const float* bt2  = (const float*)d_in[24];
    float* out = (float*)d_out;

    cudaFuncSetAttribute(attn4_kernel, cudaFuncAttributeMaxDynamicSharedMemorySize, SMEM4);

    // 1) all 5 matvecs in one launch
    matvec5_kernel<<<(5*DD + 7)/8, 256>>>(Wq, Wk, Wv, bk, bq, wld, wad, wtd);
    // 2) Mt = Wq x Wk^T
    { dim3 g(DD/64, DD/64); nt_gemm64<<<g, 256>>>(Wq, Wk, DD, DD, 0); }
    // 3) fk2 = inv*(output x Mt^T + c1), written as fp16
    { dim3 g(DD/64, NCOL/64); nt_gemm64<<<g, 256>>>(outp, nullptr, DD, DD, 1); }
    // 4) column bias + projected V values
    colbias_kernel<<<NCOL, 256>>>(outp, mask, bk, bq, bv, wld, wad, wtd);
    // 5) fp16 conversion of laws
    tohalf_laws<<<(ROWS*DD/4)/256, 256>>>(laws);
    // 6) HMMA fused scores GEMM + softmax + weighted sums + tanh
    attn4_kernel<<<ROWS/128, 256, SMEM4>>>(bld, badp, btdp);
    // 7) reduce over r per (b,l)
    head_reduce_kernel<<<BB*LL, 256>>>(wl1, bl1, wa1, ba1, wt1, bt1, out);
    // 8) tiny classifier heads
    final_kernel<<<1, 288>>>(Wa2, ba2, Wt2, bt2, out);
}

// round 8
// speedup vs baseline: 5.5233x; 1.0965x over previous
#include <cuda_runtime.h>
#include <cuda_fp16.h>
#include <math.h>
#include <stdint.h>

// Problem constants
#define LL 103
#define RR 512
#define BB 2
#define SS 512
#define DD 768
#define ROWS (LL*RR)        // 52736
#define NCOL (BB*SS)        // 1024
#define INV_SQRT_D 0.03608439182435161269f

// ---------------- device scratch (static: no allocation allowed) -------------
__device__ float g_Mt[DD*DD];
__device__ float g_c1[DD];
__device__ float g_vbq[DD], g_vlaw[DD], g_vaccu[DD], g_vterm[DD];
__device__ float g_colb[NCOL], g_pvl[NCOL], g_pva[NCOL], g_pvt[NCOL];
__device__ float g_Tl[BB*ROWS], g_Ta[BB*ROWS], g_Tt[BB*ROWS];
__device__ float g_accu1v[BB*LL], g_term1v[BB*LL];
__device__ __half g_fk2F[NCOL*DD];    // 1.5MB

// ======================= PTX helpers ========================================
__device__ __forceinline__ uint32_t smem_u32(const void* p) {
    uint32_t a;
    asm("{ .reg .u64 t; cvta.to.shared.u64 t, %1; cvt.u32.u64 %0, t; }"
        : "=r"(a) : "l"(p));
    return a;
}
__device__ __forceinline__ void cp16(uint32_t dst, const void* src) {
    asm volatile("cp.async.cg.shared.global [%0], [%1], 16;" :: "r"(dst), "l"(src));
}
#define CP_COMMIT() asm volatile("cp.async.commit_group;" ::: "memory")

#define LDSM4(r0_, r1_, r2_, r3_, addr)                                        \
    asm volatile("ldmatrix.sync.aligned.m8n8.x4.shared.b16 {%0,%1,%2,%3}, [%4];" \
        : "=r"(r0_), "=r"(r1_), "=r"(r2_), "=r"(r3_) : "r"(addr))

__device__ __forceinline__ void mma16816(float* c, const uint32_t* a,
                                         uint32_t b0, uint32_t b1) {
    asm volatile(
        "mma.sync.aligned.m16n8k16.row.col.f32.f16.f16.f32 "
        "{%0,%1,%2,%3}, {%4,%5,%6,%7}, {%8,%9}, {%0,%1,%2,%3};"
        : "+f"(c[0]), "+f"(c[1]), "+f"(c[2]), "+f"(c[3])
        : "r"(a[0]), "r"(a[1]), "r"(a[2]), "r"(a[3]), "r"(b0), "r"(b1));
}

// ======================= prep device functions ===============================
// 64x64 NT GEMM tile. mode 0: C=g_Mt fp32. mode 1: g_fk2F fp16 with alpha/bias.
__device__ void gemm64_tile(const float* __restrict__ A, const float* __restrict__ B,
                            int K, int N, int mode, int i0, int j0,
                            float* As2, float* Bs2)
{
    const float alpha = (mode == 0) ? 1.0f : INV_SQRT_D;
    int tid = threadIdx.x;
    int tx = tid & 15, ty = tid >> 4;
    float acc[4][4];
    #pragma unroll
    for (int i = 0; i < 4; i++)
        #pragma unroll
        for (int j = 0; j < 4; j++) acc[i][j] = 0.f;

    int row = tid >> 2, q = tid & 3;
    for (int kk = 0; kk < K; kk += 16) {
        __syncthreads();
        float4 va = *reinterpret_cast<const float4*>(&A[(size_t)(i0+row)*K + kk + q*4]);
        As2[(q*4+0)*68+row] = va.x; As2[(q*4+1)*68+row] = va.y;
        As2[(q*4+2)*68+row] = va.z; As2[(q*4+3)*68+row] = va.w;
        float4 vb = *reinterpret_cast<const float4*>(&B[(size_t)(j0+row)*K + kk + q*4]);
        Bs2[(q*4+0)*68+row] = vb.x; Bs2[(q*4+1)*68+row] = vb.y;
        Bs2[(q*4+2)*68+row] = vb.z; Bs2[(q*4+3)*68+row] = vb.w;
        __syncthreads();
        #pragma unroll
        for (int k = 0; k < 16; k++) {
            float4 a = *reinterpret_cast<const float4*>(&As2[k*68 + ty*4]);
            float4 b = *reinterpret_cast<const float4*>(&Bs2[k*68 + tx*4]);
            float av[4] = {a.x, a.y, a.z, a.w};
            float bv[4] = {b.x, b.y, b.z, b.w};
            #pragma unroll
            for (int i = 0; i < 4; i++)
                #pragma unroll
                for (int j = 0; j < 4; j++) acc[i][j] += av[i]*bv[j];
        }
    }
    #pragma unroll
    for (int i = 0; i < 4; i++)
        #pragma unroll
        for (int j = 0; j < 4; j++) {
            int cj = j0 + tx*4 + j;
            size_t idx = (size_t)(i0 + ty*4 + i)*N + cj;
            if (mode == 0) {
                g_Mt[idx] = alpha*acc[i][j];
            } else {
                float val = alpha*(acc[i][j] + g_c1[cj]);
                g_fk2F[idx] = __float2half_rn(val);
            }
        }
}

// ---- P1: blocks 0..143 Mt GEMM; blocks 144..623 matvec5 ---------------------
__global__ __launch_bounds__(256) void prep1_kernel(
    const float* __restrict__ Wq, const float* __restrict__ Wk,
    const float* __restrict__ Wv, const float* __restrict__ bk,
    const float* __restrict__ bq, const float* __restrict__ wld,
    const float* __restrict__ wad, const float* __restrict__ wtd)
{
    __shared__ float As2[16*68];
    __shared__ float Bs2[16*68];
    int bx = blockIdx.x;
    if (bx < 144) {
        gemm64_tile(Wq, Wk, DD, DD, 0, (bx/12)*64, (bx%12)*64, As2, Bs2);
        return;
    }
    int g = (bx - 144) * 8 + (threadIdx.x >> 5);
    int lane = threadIdx.x & 31;
    if (g >= 5*DD) return;
    int which = g / DD, row = g - which*DD;
    const float* M = (which == 0) ? Wq : (which == 1) ? Wk : Wv;
    const float* v = (which == 0) ? bk : (which == 1) ? bq :
                     (which == 2) ? wld : (which == 3) ? wad : wtd;
    float s = 0.f;
    for (int k = lane; k < DD; k += 32) s += M[(size_t)row*DD + k] * v[k];
    #pragma unroll
    for (int off = 16; off; off >>= 1) s += __shfl_xor_sync(0xffffffffu, s, off);
    if (lane == 0) {
        if      (which == 0) g_c1[row]    = s;
        else if (which == 1) g_vbq[row]   = s;
        else if (which == 2) g_vlaw[row]  = s;
        else if (which == 3) g_vaccu[row] = s;
        else                 g_vterm[row] = s;
    }
}

// ---- P2: blocks 0..191 fk2 GEMM; blocks 192..1215 colbias -------------------
__global__ __launch_bounds__(256) void prep2_kernel(
    const float* __restrict__ outp, const int* __restrict__ mask,
    const float* __restrict__ bk, const float* __restrict__ bq,
    const float* __restrict__ bv,
    const float* __restrict__ wl, const float* __restrict__ wa,
    const float* __restrict__ wt)
{
    __shared__ float As2[16*68];
    __shared__ float Bs2[16*68];
    __shared__ float red[8][8];
    int bx = blockIdx.x;
    if (bx < 192) {
        gemm64_tile(outp, g_Mt, DD, DD, 1, (bx/12)*64, (bx%12)*64, As2, Bs2);
        return;
    }
    int j = bx - 192;
    int tid = threadIdx.x;
    float s[8] = {0,0,0,0,0,0,0,0};
    for (int k = tid; k < DD; k += 256) {
        float o = outp[(size_t)j*DD + k];
        s[0] += o * g_vbq[k];
        s[1] += o * g_vlaw[k];
        s[2] += o * g_vaccu[k];
        s[3] += o * g_vterm[k];
        s[4] += bk[k]*bq[k];
        s[5] += bv[k]*wl[k];
        s[6] += bv[k]*wa[k];
        s[7] += bv[k]*wt[k];
    }
    int warp = tid >> 5, lane = tid & 31;
    #pragma unroll
    for (int v = 0; v < 8; v++) {
        float x = s[v];
        #pragma unroll
        for (int off = 16; off; off >>= 1) x += __shfl_xor_sync(0xffffffffu, x, off);
        if (lane == 0) red[v][warp] = x;
    }
    __syncthreads();
    if (tid == 0) {
        float t[8];
        #pragma unroll
        for (int v = 0; v < 8; v++) {
            float x = 0.f;
            #pragma unroll
            for (int w = 0; w < 8; w++) x += red[v][w];
            t[v] = x;
        }
        g_colb[j] = (t[0] + t[4]) * INV_SQRT_D + (1.0f - (float)mask[j]) * (-10000.0f);
        g_pvl[j] = t[1] + t[5];
        g_pva[j] = t[2] + t[6];
        g_pvt[j] = t[3] + t[7];
    }
}

// ======================= main HMMA attention kernel ==========================
// CTA: M=128 rows, chunkN=256 (4 chunks), warp grid 2m x 4n, warp tile 64x64.
// K-stage 64, 3-stage pipeline (B: cp.async; A: LDG fp32 -> cvt -> STS fp16).
#define APITCH4 144
#define A_ST4   (128*APITCH4)          // 18432
#define B_ST4   (256*APITCH4)          // 36864
#define STG4    (A_ST4 + B_ST4)        // 55296
#define SM_PV4  (3*STG4)               // 165888
#define SM_MRG4 (SM_PV4 + 16384)       // 182272
#define SMEM4   (SM_MRG4 + 8192)       // 190464

__device__ __forceinline__ void loadB(int it, uint32_t sb)
{
    const int chunk = it / 12, kt = it - chunk*12;
    const int j0 = chunk * 256, kc = kt * 64;
    const uint32_t st = sb + (uint32_t)(it % 3) * STG4 + A_ST4;
    const int tid = threadIdx.x;
    #pragma unroll
    for (int p = 0; p < 8; p++) {       // B: 256 rows x 8 segs of 16B
        int idx = p*256 + tid;
        int row = idx >> 3, seg = idx & 7;
        const char* src = (const char*)(g_fk2F + (size_t)(j0+row)*DD + kc) + seg*16;
        cp16(st + A_ST4*0 + (uint32_t)(row*APITCH4 + seg*16), src);
    }
}

__device__ __forceinline__ void ldgA(int it, int r0, const float* __restrict__ laws,
                                     float4 fA[4][2])
{
    const int kt = it % 12;
    const int kc = kt * 64;
    const int tid = threadIdx.x;
    #pragma unroll
    for (int q = 0; q < 4; q++) {
        int idx = q*256 + tid;
        int row = idx >> 3, c8 = idx & 7;
        const float* src = laws + (size_t)(r0+row)*DD + kc + c8*8;
        fA[q][0] = *reinterpret_cast<const float4*>(src);
        fA[q][1] = *reinterpret_cast<const float4*>(src + 4);
    }
}

__device__ __forceinline__ void stsA(int it, char* smem, const float4 fA[4][2])
{
    char* base = smem + (size_t)(it % 3) * STG4;
    const int tid = threadIdx.x;
    #pragma unroll
    for (int q = 0; q < 4; q++) {
        int idx = q*256 + tid;
        int row = idx >> 3, c8 = idx & 7;
        __half2 h0 = __floats2half2_rn(fA[q][0].x, fA[q][0].y);
        __half2 h1 = __floats2half2_rn(fA[q][0].z, fA[q][0].w);
        __half2 h2 = __floats2half2_rn(fA[q][1].x, fA[q][1].y);
        __half2 h3 = __floats2half2_rn(fA[q][1].z, fA[q][1].w);
        uint4 pkt;
        pkt.x = *reinterpret_cast<uint32_t*>(&h0);
        pkt.y = *reinterpret_cast<uint32_t*>(&h1);
        pkt.z = *reinterpret_cast<uint32_t*>(&h2);
        pkt.w = *reinterpret_cast<uint32_t*>(&h3);
        *reinterpret_cast<uint4*>(base + row*APITCH4 + c8*16) = pkt;
    }
}

__global__ __launch_bounds__(256, 1) void attn5_kernel(
    const float* __restrict__ laws,
    const float* __restrict__ bld, const float* __restrict__ bad,
    const float* __restrict__ btd)
{
    extern __shared__ char smem[];
    uint32_t sb = smem_u32(smem);
    float* pvc = reinterpret_cast<float*>(smem + SM_PV4);
    float* mrg = reinterpret_cast<float*>(smem + SM_MRG4);
    const int tid = threadIdx.x;
    const int lane = tid & 31, wid = tid >> 5;
    const int wm = wid & 1, wn = wid >> 1;    // 2 m-warps x 4 n-warps
    const int r0 = blockIdx.x * 128;

    for (int i = tid; i < 1024; i += 256) {
        pvc[i]        = g_colb[i];
        pvc[1024 + i] = g_pvl[i];
        pvc[2048 + i] = g_pva[i];
        pvc[3072 + i] = g_pvt[i];
    }

    float4 fA[4][2];
    // prologue: A(0) LDG+STS, B(0), B(1) in flight
    ldgA(0, r0, laws, fA);
    loadB(0, sb); CP_COMMIT();
    loadB(1, sb); CP_COMMIT();
    stsA(0, smem, fA);

    const float bias_l = *bld, bias_a = *bad, bias_t = *btd;

    float acc[4][8][4];
    float st_z[8], st_w0[8], st_w1[8], st_w2[8];
    #pragma unroll
    for (int e = 0; e < 8; e++) { st_z[e]=0.f; st_w0[e]=0.f; st_w1[e]=0.f; st_w2[e]=0.f; }

    const int arow = wm*64 + (lane & 15);
    const int brow = wn*64 + (lane & 7) + ((lane >> 4) << 3);
    const int akb  = (lane >> 4) * 16;
    const int bkb  = ((lane >> 3) & 1) * 16;

    for (int it = 0; it < 48; it++) {
        const int chunk = it / 12;
        const int kt = it - chunk*12;
        if (kt == 0) {
            #pragma unroll
            for (int mt = 0; mt < 4; mt++)
                #pragma unroll
                for (int nt = 0; nt < 8; nt++)
                    #pragma unroll
                    for (int k = 0; k < 4; k++) acc[mt][nt][k] = 0.f;
        }

        if (it == 47) asm volatile("cp.async.wait_group 0;" ::: "memory");
        else          asm volatile("cp.async.wait_group 1;" ::: "memory");
        __syncthreads();

        // prefetch next A (fp32 regs) and B (cp.async)
        if (it + 1 < 48) ldgA(it + 1, r0, laws, fA);
        if (it + 2 < 48) { loadB(it + 2, sb); CP_COMMIT(); }

        const uint32_t st = sb + (uint32_t)(it % 3) * STG4;
        #pragma unroll
        for (int ks = 0; ks < 4; ks++) {
            uint32_t af[4][4];
            uint32_t bf[4][4];
            #pragma unroll
            for (int mt = 0; mt < 4; mt++) {
                uint32_t ad = st + (uint32_t)((arow + mt*16)*APITCH4 + ks*32 + akb);
                LDSM4(af[mt][0], af[mt][1], af[mt][2], af[mt][3], ad);
            }
            #pragma unroll
            for (int p = 0; p < 4; p++) {
                uint32_t bd = st + A_ST4 + (uint32_t)((brow + p*16)*APITCH4 + ks*32 + bkb);
                LDSM4(bf[p][0], bf[p][1], bf[p][2], bf[p][3], bd);
            }
            #pragma unroll
            for (int mt = 0; mt < 4; mt++)
                #pragma unroll
                for (int nt = 0; nt < 8; nt++)
                    mma16816(acc[mt][nt], af[mt], bf[nt>>1][(nt&1)*2], bf[nt>>1][(nt&1)*2+1]);
        }

        // store next A tile as fp16 (consumed after next top-of-loop sync)
        if (it + 1 < 48) stsA(it + 1, smem, fA);

        if (kt == 11) {
            // per-chunk epilogue (no max: logits O(1), masked cols underflow to 0)
            const int jb = chunk*256 + wn*64 + 2*(lane & 3);
            #pragma unroll
            for (int mt = 0; mt < 4; mt++) {
                #pragma unroll
                for (int h = 0; h < 2; h++) {
                    const int e = mt*2 + h;
                    float z = 0.f, w0 = 0.f, w1 = 0.f, w2 = 0.f;
                    #pragma unroll
                    for (int nt = 0; nt < 8; nt++) {
                        int j = jb + nt*8;
                        float e0 = __expf(acc[mt][nt][2*h]   + pvc[j]);
                        float e1 = __expf(acc[mt][nt][2*h+1] + pvc[j+1]);
                        z  += e0 + e1;
                        w0 += e0*pvc[1024+j] + e1*pvc[1025+j];
                        w1 += e0*pvc[2048+j] + e1*pvc[2049+j];
                        w2 += e0*pvc[3072+j] + e1*pvc[3073+j];
                    }
                    st_z[e] += z; st_w0[e] += w0; st_w1[e] += w1; st_w2[e] += w2;
                }
            }
            if (chunk & 1) {
                #pragma unroll
                for (int e = 0; e < 8; e++) {
                    #pragma unroll
                    for (int off = 1; off < 4; off <<= 1) {
                        st_z[e]  += __shfl_xor_sync(0xffffffffu, st_z[e],  off);
                        st_w0[e] += __shfl_xor_sync(0xffffffffu, st_w0[e], off);
                        st_w1[e] += __shfl_xor_sync(0xffffffffu, st_w1[e], off);
                        st_w2[e] += __shfl_xor_sync(0xffffffffu, st_w2[e], off);
                    }
                }
                if ((lane & 3) == 0) {
                    #pragma unroll
                    for (int mt = 0; mt < 4; mt++)
                        #pragma unroll
                        for (int h = 0; h < 2; h++) {
                            const int e = mt*2 + h;
                            int row = wm*64 + mt*16 + (lane >> 2) + 8*h;
                            float* m = &mrg[row*16 + wn*4];
                            m[0] = st_z[e]; m[1] = st_w0[e]; m[2] = st_w1[e]; m[3] = st_w2[e];
                        }
                }
                __syncthreads();
                if (tid < 128) {
                    int row = tid;
                    float z = 0.f, w0 = 0.f, w1 = 0.f, w2 = 0.f;
                    #pragma unroll
                    for (int w = 0; w < 4; w++) {
                        const float* m = &mrg[row*16 + w*4];
                        z += m[0]; w0 += m[1]; w1 += m[2]; w2 += m[3];
                    }
                    int b = chunk >> 1;
                    int rg = r0 + row;
                    float inv = 1.0f / z;
                    g_Tl[b*ROWS + rg] = tanhf(w0*inv + bias_l);
                    g_Ta[b*ROWS + rg] = tanhf(w1*inv + bias_a);
                    g_Tt[b*ROWS + rg] = tanhf(w2*inv + bias_t);
                }
                #pragma unroll
                for (int e = 0; e < 8; e++) {
                    st_z[e]=0.f; st_w0[e]=0.f; st_w1[e]=0.f; st_w2[e]=0.f;
                }
            }
        }
    }
}

// ---------------- reduce over r (512) per (b,l) ------------------------------
__global__ void head_reduce_kernel(const float* __restrict__ w1l, const float* __restrict__ b1l,
                                   const float* __restrict__ w1a, const float* __restrict__ b1a,
                                   const float* __restrict__ w1t, const float* __restrict__ b1t,
                                   float* __restrict__ out)
{
    int bl = blockIdx.x;
    int b = bl / LL, l = bl % LL;
    size_t base = (size_t)b*ROWS + (size_t)l*RR;
    int tid = threadIdx.x;
    float sl = 0.f, sa = 0.f, st = 0.f;
    for (int r = tid; r < RR; r += 256) {
        sl += g_Tl[base + r] * w1l[r];
        sa += g_Ta[base + r] * w1a[r];
        st += g_Tt[base + r] * w1t[r];
    }
    __shared__ float red[3][8];
    int warp = tid >> 5, lane = tid & 31;
    #pragma unroll
    for (int off = 16; off; off >>= 1) {
        sl += __shfl_xor_sync(0xffffffffu, sl, off);
        sa += __shfl_xor_sync(0xffffffffu, sa, off);
        st += __shfl_xor_sync(0xffffffffu, st, off);
    }
    if (lane == 0) { red[0][warp] = sl; red[1][warp] = sa; red[2][warp] = st; }
    __syncthreads();
    if (tid == 0) {
        float SL = 0.f, SA = 0.f, ST = 0.f;
        #pragma unroll
        for (int w = 0; w < 8; w++) { SL += red[0][w]; SA += red[1][w]; ST += red[2][w]; }
        out[b*LL + l] = SL + b1l[0];
        g_accu1v[b*LL + l] = tanhf(SA + b1a[0]);
        g_term1v[b*LL + l] = tanhf(ST + b1t[0]);
    }
}

// ---------------- final tiny classifier heads --------------------------------
__global__ void final_kernel(const float* __restrict__ Wa2, const float* __restrict__ ba2,
                             const float* __restrict__ Wt2, const float* __restrict__ bt2,
                             float* __restrict__ out)
{
    int t = threadIdx.x;
    if (t < BB*119) {
        int b = t / 119, j = t % 119;
        float s = 0.f;
        for (int l = 0; l < LL; l++) s += g_accu1v[b*LL + l] * Wa2[j*LL + l];
        out[BB*LL + b*119 + j] = s + ba2[j];
    } else if (t < BB*119 + BB*11) {
        int u = t - BB*119;
        int b = u / 11, j = u % 11;
        float s = 0.f;
        for (int l = 0; l < LL; l++) s += g_term1v[b*LL + l] * Wt2[j*LL + l];
        out[BB*LL + BB*119 + b*11 + j] = s + bt2[j];
    }
}

// ---------------- launcher ---------------------------------------------------
extern "C" void kernel_launch(void* const* d_in, const int* in_sizes, int n_in,
                              void* d_out, int out_size)
{
    const float* outp = (const float*)d_in[0];
    const int*   mask = (const int*)  d_in[1];
    const float* laws = (const float*)d_in[2];
    const float* Wq   = (const float*)d_in[3];
    const float* bq   = (const float*)d_in[4];
    const float* Wk   = (const float*)d_in[5];
    const float* bk   = (const float*)d_in[6];
    const float* Wv   = (const float*)d_in[7];
    const float* bv   = (const float*)d_in[8];
    const float* wld  = (const float*)d_in[9];
    const float* bld  = (const float*)d_in[10];
    const float* wl1  = (const float*)d_in[11];
    const float* bl1  = (const float*)d_in[12];
    const float* wad  = (const float*)d_in[13];
    const float* badp = (const float*)d_in[14];
    const float* wa1  = (const float*)d_in[15];
    const float* ba1  = (const float*)d_in[16];
    const float* Wa2  = (const float*)d_in[17];
    const float* ba2  = (const float*)d_in[18];
    const float* wtd  = (const float*)d_in[19];
    const float* btdp = (const float*)d_in[20];
    const float* wt1  = (const float*)d_in[21];
    const float* bt1  = (const float*)d_in[22];
    const float* Wt2  = (const float*)d_in[23];
    const float* bt2  = (const float*)d_in[24];
    float* out = (float*)d_out;

    cudaFuncSetAttribute(attn5_kernel, cudaFuncAttributeMaxDynamicSharedMemorySize, SMEM4);

    // 1) Mt GEMM (144 blocks) + 5 matvecs (480 blocks) in one launch
    prep1_kernel<<<624, 256>>>(Wq, Wk, Wv, bk, bq, wld, wad, wtd);
    // 2) fk2 GEMM (192 blocks) + colbias (1024 blocks) in one launch
    prep2_kernel<<<1216, 256>>>(outp, mask, bk, bq, bv, wld, wad, wtd);
    // 3) HMMA fused scores GEMM (fp32->fp16 A convert in-kernel) + softmax heads
    attn5_kernel<<<ROWS/128, 256, SMEM4>>>(laws, bld, badp, btdp);
    // 4) reduce over r per (b,l)
    head_reduce_kernel<<<BB*LL, 256>>>(wl1, bl1, wa1, ba1, wt1, bt1, out);
    // 5) tiny classifier heads
    final_kernel<<<1, 288>>>(Wa2, ba2, Wt2, bt2, out);
}

// round 9
// speedup vs baseline: 6.9910x; 1.2657x over previous
#include <cuda_runtime.h>
#include <cuda_fp16.h>
#include <math.h>
#include <stdint.h>

// Problem constants
#define LL 103
#define RR 512
#define BB 2
#define SS 512
#define DD 768
#define ROWS (LL*RR)        // 52736
#define NCOL (BB*SS)        // 1024
#define INV_SQRT_D 0.03608439182435161269f

// ---------------- device scratch (static: no allocation allowed) -------------
__device__ float g_c1[DD];
__device__ float g_vbq[DD], g_vlaw[DD], g_vaccu[DD], g_vterm[DD];
__device__ float g_colb[NCOL], g_pvl[NCOL], g_pva[NCOL], g_pvt[NCOL];
__device__ float g_Tl[BB*ROWS], g_Ta[BB*ROWS], g_Tt[BB*ROWS];
__device__ float g_accu1v[BB*LL], g_term1v[BB*LL];
__device__ __half g_fk2F[NCOL*DD];    // 1.5MB
__device__ __half g_WqF[DD*DD];
__device__ __half g_WkF[DD*DD];
__device__ __half g_outF[NCOL*DD];
__device__ __half g_MtF[DD*DD];

// ======================= PTX helpers ========================================
__device__ __forceinline__ uint32_t smem_u32(const void* p) {
    uint32_t a;
    asm("{ .reg .u64 t; cvta.to.shared.u64 t, %1; cvt.u32.u64 %0, t; }"
        : "=r"(a) : "l"(p));
    return a;
}
__device__ __forceinline__ void cp16(uint32_t dst, const void* src) {
    asm volatile("cp.async.cg.shared.global [%0], [%1], 16;" :: "r"(dst), "l"(src));
}
#define CP_COMMIT() asm volatile("cp.async.commit_group;" ::: "memory")

#define LDSM4(r0_, r1_, r2_, r3_, addr)                                        \
    asm volatile("ldmatrix.sync.aligned.m8n8.x4.shared.b16 {%0,%1,%2,%3}, [%4];" \
        : "=r"(r0_), "=r"(r1_), "=r"(r2_), "=r"(r3_) : "r"(addr))

__device__ __forceinline__ void mma16816(float* c, const uint32_t* a,
                                         uint32_t b0, uint32_t b1) {
    asm volatile(
        "mma.sync.aligned.m16n8k16.row.col.f32.f16.f16.f32 "
        "{%0,%1,%2,%3}, {%4,%5,%6,%7}, {%8,%9}, {%0,%1,%2,%3};"
        : "+f"(c[0]), "+f"(c[1]), "+f"(c[2]), "+f"(c[3])
        : "r"(a[0]), "r"(a[1]), "r"(a[2]), "r"(a[3]), "r"(b0), "r"(b1));
}

// ======================= prep0: fp16 converts + 5 matvecs ====================
// blocks 0..1919: convert Wq|Wk|output float4 -> half2 pairs
// blocks 1920..2399: matvec rows (8 warps per block)
__global__ __launch_bounds__(256) void prep0_kernel(
    const float* __restrict__ Wq, const float* __restrict__ Wk,
    const float* __restrict__ Wv, const float* __restrict__ outp,
    const float* __restrict__ bk, const float* __restrict__ bq,
    const float* __restrict__ wld, const float* __restrict__ wad,
    const float* __restrict__ wtd)
{
    int bx = blockIdx.x;
    if (bx < 1920) {
        size_t i = (size_t)bx * 256 + threadIdx.x;   // float4 index
        const float* src; __half* dst; size_t off;
        if (i < 147456)      { src = Wq;   dst = g_WqF;  off = i; }
        else if (i < 294912) { src = Wk;   dst = g_WkF;  off = i - 147456; }
        else                 { src = outp; dst = g_outF; off = i - 294912; }
        float4 v = reinterpret_cast<const float4*>(src)[off];
        __half2* d = reinterpret_cast<__half2*>(dst);
        d[2*off]   = __floats2half2_rn(v.x, v.y);
        d[2*off+1] = __floats2half2_rn(v.z, v.w);
        return;
    }
    int g = (bx - 1920) * 8 + (threadIdx.x >> 5);
    int lane = threadIdx.x & 31;
    if (g >= 5*DD) return;
    int which = g / DD, row = g - which*DD;
    const float* M = (which == 0) ? Wq : (which == 1) ? Wk : Wv;
    const float* v = (which == 0) ? bk : (which == 1) ? bq :
                     (which == 2) ? wld : (which == 3) ? wad : wtd;
    float s = 0.f;
    for (int k = lane; k < DD; k += 32) s += M[(size_t)row*DD + k] * v[k];
    #pragma unroll
    for (int off = 16; off; off >>= 1) s += __shfl_xor_sync(0xffffffffu, s, off);
    if (lane == 0) {
        if      (which == 0) g_c1[row]    = s;
        else if (which == 1) g_vbq[row]   = s;
        else if (which == 2) g_vlaw[row]  = s;
        else if (which == 3) g_vaccu[row] = s;
        else                 g_vterm[row] = s;
    }
}

// ======================= HMMA 64x128 NT tile (prep GEMMs) ====================
// CTA 64x128, 8 warps as 2m x 4n, warp tile 32x32. 3-stage cp.async, K-step 64.
// mode 0: C=g_MtF (plain fp16). mode 1: C=g_fk2F, val = inv*(acc + c1[col]).
#define HPITCH 144
#define H_AST  (64*HPITCH)             // 9216
#define H_STG  (H_AST + 128*HPITCH)    // 27648
#define H_SMEM (3*H_STG)               // 82944

__device__ __forceinline__ void hload(const __half* __restrict__ A,
                                      const __half* __restrict__ B, int K,
                                      int row0, int col0, int kt,
                                      uint32_t sb)
{
    uint32_t st = sb + (uint32_t)(kt % 3) * H_STG;
    int tid = threadIdx.x;
    #pragma unroll
    for (int p = 0; p < 2; p++) {       // A: 64 rows x 8 segs of 16B
        int idx = p*256 + tid;
        int row = idx >> 3, seg = idx & 7;
        const char* src = (const char*)(A + (size_t)(row0+row)*K + kt*64) + seg*16;
        cp16(st + (uint32_t)(row*HPITCH + seg*16), src);
    }
    #pragma unroll
    for (int p = 0; p < 4; p++) {       // B: 128 rows x 8 segs
        int idx = p*256 + tid;
        int row = idx >> 3, seg = idx & 7;
        const char* src = (const char*)(B + (size_t)(col0+row)*K + kt*64) + seg*16;
        cp16(st + H_AST + (uint32_t)(row*HPITCH + seg*16), src);
    }
}

__device__ void hgemm_tile(const __half* __restrict__ A,
                           const __half* __restrict__ B,
                           int K, int row0, int col0, int N, int mode,
                           char* dsm)
{
    uint32_t sb = smem_u32(dsm);
    const int tid = threadIdx.x;
    const int lane = tid & 31, wid = tid >> 5;
    const int wm = wid & 1, wn = wid >> 1;   // 2m x 4n warps

    hload(A, B, K, row0, col0, 0, sb); CP_COMMIT();
    hload(A, B, K, row0, col0, 1, sb); CP_COMMIT();

    float acc[2][4][4];
    #pragma unroll
    for (int mt = 0; mt < 2; mt++)
        #pragma unroll
        for (int nt = 0; nt < 4; nt++)
            #pragma unroll
            for (int k = 0; k < 4; k++) acc[mt][nt][k] = 0.f;

    const int arow = wm*32 + (lane & 15);
    const int brow = wn*32 + (lane & 7) + ((lane >> 4) << 3);
    const int akb  = (lane >> 4) * 16;
    const int bkb  = ((lane >> 3) & 1) * 16;
    const int nk = K / 64;

    for (int it = 0; it < nk; it++) {
        if (it == nk-1) asm volatile("cp.async.wait_group 0;" ::: "memory");
        else            asm volatile("cp.async.wait_group 1;" ::: "memory");
        __syncthreads();
        if (it + 2 < nk) { hload(A, B, K, row0, col0, it + 2, sb); CP_COMMIT(); }

        const uint32_t st = sb + (uint32_t)(it % 3) * H_STG;
        #pragma unroll
        for (int ks = 0; ks < 4; ks++) {
            uint32_t af[2][4];
            uint32_t bf[2][4];
            #pragma unroll
            for (int mt = 0; mt < 2; mt++) {
                uint32_t ad = st + (uint32_t)((arow + mt*16)*HPITCH + ks*32 + akb);
                LDSM4(af[mt][0], af[mt][1], af[mt][2], af[mt][3], ad);
            }
            #pragma unroll
            for (int p = 0; p < 2; p++) {
                uint32_t bd = st + H_AST + (uint32_t)((brow + p*16)*HPITCH + ks*32 + bkb);
                LDSM4(bf[p][0], bf[p][1], bf[p][2], bf[p][3], bd);
            }
            #pragma unroll
            for (int mt = 0; mt < 2; mt++)
                #pragma unroll
                for (int nt = 0; nt < 4; nt++)
                    mma16816(acc[mt][nt], af[mt], bf[nt>>1][(nt&1)*2], bf[nt>>1][(nt&1)*2+1]);
        }
    }

    // epilogue: direct global stores (half2)
    #pragma unroll
    for (int mt = 0; mt < 2; mt++)
        #pragma unroll
        for (int nt = 0; nt < 4; nt++)
            #pragma unroll
            for (int h = 0; h < 2; h++) {
                int row = row0 + wm*32 + mt*16 + (lane >> 2) + 8*h;
                int col = col0 + wn*32 + nt*8 + 2*(lane & 3);
                float v0 = acc[mt][nt][2*h], v1 = acc[mt][nt][2*h+1];
                if (mode == 1) {
                    v0 = INV_SQRT_D * (v0 + g_c1[col]);
                    v1 = INV_SQRT_D * (v1 + g_c1[col+1]);
                    *reinterpret_cast<__half2*>(&g_fk2F[(size_t)row*N + col]) =
                        __floats2half2_rn(v0, v1);
                } else {
                    *reinterpret_cast<__half2*>(&g_MtF[(size_t)row*N + col]) =
                        __floats2half2_rn(v0, v1);
                }
            }
}

// ---- prep1: blocks 0..71 Mt HMMA; blocks 72..1095 colbias -------------------
__global__ __launch_bounds__(256) void prep1_kernel(
    const float* __restrict__ outp, const int* __restrict__ mask,
    const float* __restrict__ bk, const float* __restrict__ bq,
    const float* __restrict__ bv,
    const float* __restrict__ wl, const float* __restrict__ wa,
    const float* __restrict__ wt)
{
    extern __shared__ char dsm[];
    int bx = blockIdx.x;
    if (bx < 72) {
        hgemm_tile(g_WqF, g_WkF, DD, (bx/6)*64, (bx%6)*128, DD, 0, dsm);
        return;
    }
    __shared__ float red[8][8];
    int j = bx - 72;
    int tid = threadIdx.x;
    float s[8] = {0,0,0,0,0,0,0,0};
    for (int k = tid; k < DD; k += 256) {
        float o = outp[(size_t)j*DD + k];
        s[0] += o * g_vbq[k];
        s[1] += o * g_vlaw[k];
        s[2] += o * g_vaccu[k];
        s[3] += o * g_vterm[k];
        s[4] += bk[k]*bq[k];
        s[5] += bv[k]*wl[k];
        s[6] += bv[k]*wa[k];
        s[7] += bv[k]*wt[k];
    }
    int warp = tid >> 5, lane = tid & 31;
    #pragma unroll
    for (int v = 0; v < 8; v++) {
        float x = s[v];
        #pragma unroll
        for (int off = 16; off; off >>= 1) x += __shfl_xor_sync(0xffffffffu, x, off);
        if (lane == 0) red[v][warp] = x;
    }
    __syncthreads();
    if (tid == 0) {
        float t[8];
        #pragma unroll
        for (int v = 0; v < 8; v++) {
            float x = 0.f;
            #pragma unroll
            for (int w = 0; w < 8; w++) x += red[v][w];
            t[v] = x;
        }
        g_colb[j] = (t[0] + t[4]) * INV_SQRT_D + (1.0f - (float)mask[j]) * (-10000.0f);
        g_pvl[j] = t[1] + t[5];
        g_pva[j] = t[2] + t[6];
        g_pvt[j] = t[3] + t[7];
    }
}

// ---- prep2: fk2 = inv*(outF @ MtF^T + c1), 96 HMMA tiles --------------------
__global__ __launch_bounds__(256) void prep2_kernel()
{
    extern __shared__ char dsm[];
    int bx = blockIdx.x;
    hgemm_tile(g_outF, g_MtF, DD, (bx/6)*64, (bx%6)*128, DD, 1, dsm);
}

// ======================= main HMMA attention kernel ==========================
// CTA: M=128 rows, chunkN=256 (4 chunks), warp grid 2m x 4n, warp tile 64x64.
// K-stage 64, 3-stage pipeline (B: cp.async; A: LDG fp32 -> cvt -> STS fp16).
#define APITCH4 144
#define A_ST4   (128*APITCH4)          // 18432
#define B_ST4   (256*APITCH4)          // 36864
#define STG4    (A_ST4 + B_ST4)        // 55296
#define SM_PV4  (3*STG4)               // 165888
#define SM_MRG4 (SM_PV4 + 16384)       // 182272
#define SMEM4   (SM_MRG4 + 8192)       // 190464

__device__ __forceinline__ void loadB(int it, uint32_t sb)
{
    const int chunk = it / 12, kt = it - chunk*12;
    const int j0 = chunk * 256, kc = kt * 64;
    const uint32_t st = sb + (uint32_t)(it % 3) * STG4 + A_ST4;
    const int tid = threadIdx.x;
    #pragma unroll
    for (int p = 0; p < 8; p++) {       // B: 256 rows x 8 segs of 16B
        int idx = p*256 + tid;
        int row = idx >> 3, seg = idx & 7;
        const char* src = (const char*)(g_fk2F + (size_t)(j0+row)*DD + kc) + seg*16;
        cp16(st + (uint32_t)(row*APITCH4 + seg*16), src);
    }
}

__device__ __forceinline__ void ldgA(int it, int r0, const float* __restrict__ laws,
                                     float4 fA[4][2])
{
    const int kt = it % 12;
    const int kc = kt * 64;
    const int tid = threadIdx.x;
    #pragma unroll
    for (int q = 0; q < 4; q++) {
        int idx = q*256 + tid;
        int row = idx >> 3, c8 = idx & 7;
        const float* src = laws + (size_t)(r0+row)*DD + kc + c8*8;
        fA[q][0] = *reinterpret_cast<const float4*>(src);
        fA[q][1] = *reinterpret_cast<const float4*>(src + 4);
    }
}

__device__ __forceinline__ void stsA(int it, char* smem, const float4 fA[4][2])
{
    char* base = smem + (size_t)(it % 3) * STG4;
    const int tid = threadIdx.x;
    #pragma unroll
    for (int q = 0; q < 4; q++) {
        int idx = q*256 + tid;
        int row = idx >> 3, c8 = idx & 7;
        __half2 h0 = __floats2half2_rn(fA[q][0].x, fA[q][0].y);
        __half2 h1 = __floats2half2_rn(fA[q][0].z, fA[q][0].w);
        __half2 h2 = __floats2half2_rn(fA[q][1].x, fA[q][1].y);
        __half2 h3 = __floats2half2_rn(fA[q][1].z, fA[q][1].w);
        uint4 pkt;
        pkt.x = *reinterpret_cast<uint32_t*>(&h0);
        pkt.y = *reinterpret_cast<uint32_t*>(&h1);
        pkt.z = *reinterpret_cast<uint32_t*>(&h2);
        pkt.w = *reinterpret_cast<uint32_t*>(&h3);
        *reinterpret_cast<uint4*>(base + row*APITCH4 + c8*16) = pkt;
    }
}

__global__ __launch_bounds__(256, 1) void attn5_kernel(
    const float* __restrict__ laws,
    const float* __restrict__ bld, const float* __restrict__ bad,
    const float* __restrict__ btd)
{
    extern __shared__ char smem[];
    uint32_t sb = smem_u32(smem);
    float* pvc = reinterpret_cast<float*>(smem + SM_PV4);
    float* mrg = reinterpret_cast<float*>(smem + SM_MRG4);
    const int tid = threadIdx.x;
    const int lane = tid & 31, wid = tid >> 5;
    const int wm = wid & 1, wn = wid >> 1;    // 2 m-warps x 4 n-warps
    const int r0 = blockIdx.x * 128;

    for (int i = tid; i < 1024; i += 256) {
        pvc[i]        = g_colb[i];
        pvc[1024 + i] = g_pvl[i];
        pvc[2048 + i] = g_pva[i];
        pvc[3072 + i] = g_pvt[i];
    }

    float4 fA[4][2];
    ldgA(0, r0, laws, fA);
    loadB(0, sb); CP_COMMIT();
    loadB(1, sb); CP_COMMIT();
    stsA(0, smem, fA);

    const float bias_l = *bld, bias_a = *bad, bias_t = *btd;

    float acc[4][8][4];
    float st_z[8], st_w0[8], st_w1[8], st_w2[8];
    #pragma unroll
    for (int e = 0; e < 8; e++) { st_z[e]=0.f; st_w0[e]=0.f; st_w1[e]=0.f; st_w2[e]=0.f; }

    const int arow = wm*64 + (lane & 15);
    const int brow = wn*64 + (lane & 7) + ((lane >> 4) << 3);
    const int akb  = (lane >> 4) * 16;
    const int bkb  = ((lane >> 3) & 1) * 16;

    for (int it = 0; it < 48; it++) {
        const int chunk = it / 12;
        const int kt = it - chunk*12;
        if (kt == 0) {
            #pragma unroll
            for (int mt = 0; mt < 4; mt++)
                #pragma unroll
                for (int nt = 0; nt < 8; nt++)
                    #pragma unroll
                    for (int k = 0; k < 4; k++) acc[mt][nt][k] = 0.f;
        }

        if (it == 47) asm volatile("cp.async.wait_group 0;" ::: "memory");
        else          asm volatile("cp.async.wait_group 1;" ::: "memory");
        __syncthreads();

        if (it + 1 < 48) ldgA(it + 1, r0, laws, fA);
        if (it + 2 < 48) { loadB(it + 2, sb); CP_COMMIT(); }

        const uint32_t st = sb + (uint32_t)(it % 3) * STG4;
        #pragma unroll
        for (int ks = 0; ks < 4; ks++) {
            uint32_t af[4][4];
            uint32_t bf[4][4];
            #pragma unroll
            for (int mt = 0; mt < 4; mt++) {
                uint32_t ad = st + (uint32_t)((arow + mt*16)*APITCH4 + ks*32 + akb);
                LDSM4(af[mt][0], af[mt][1], af[mt][2], af[mt][3], ad);
            }
            #pragma unroll
            for (int p = 0; p < 4; p++) {
                uint32_t bd = st + A_ST4 + (uint32_t)((brow + p*16)*APITCH4 + ks*32 + bkb);
                LDSM4(bf[p][0], bf[p][1], bf[p][2], bf[p][3], bd);
            }
            #pragma unroll
            for (int mt = 0; mt < 4; mt++)
                #pragma unroll
                for (int nt = 0; nt < 8; nt++)
                    mma16816(acc[mt][nt], af[mt], bf[nt>>1][(nt&1)*2], bf[nt>>1][(nt&1)*2+1]);
        }

        if (it + 1 < 48) stsA(it + 1, smem, fA);

        if (kt == 11) {
            const int jb = chunk*256 + wn*64 + 2*(lane & 3);
            #pragma unroll
            for (int mt = 0; mt < 4; mt++) {
                #pragma unroll
                for (int h = 0; h < 2; h++) {
                    const int e = mt*2 + h;
                    float z = 0.f, w0 = 0.f, w1 = 0.f, w2 = 0.f;
                    #pragma unroll
                    for (int nt = 0; nt < 8; nt++) {
                        int j = jb + nt*8;
                        float e0 = __expf(acc[mt][nt][2*h]   + pvc[j]);
                        float e1 = __expf(acc[mt][nt][2*h+1] + pvc[j+1]);
                        z  += e0 + e1;
                        w0 += e0*pvc[1024+j] + e1*pvc[1025+j];
                        w1 += e0*pvc[2048+j] + e1*pvc[2049+j];
                        w2 += e0*pvc[3072+j] + e1*pvc[3073+j];
                    }
                    st_z[e] += z; st_w0[e] += w0; st_w1[e] += w1; st_w2[e] += w2;
                }
            }
            if (chunk & 1) {
                #pragma unroll
                for (int e = 0; e < 8; e++) {
                    #pragma unroll
                    for (int off = 1; off < 4; off <<= 1) {
                        st_z[e]  += __shfl_xor_sync(0xffffffffu, st_z[e],  off);
                        st_w0[e] += __shfl_xor_sync(0xffffffffu, st_w0[e], off);
                        st_w1[e] += __shfl_xor_sync(0xffffffffu, st_w1[e], off);
                        st_w2[e] += __shfl_xor_sync(0xffffffffu, st_w2[e], off);
                    }
                }
                if ((lane & 3) == 0) {
                    #pragma unroll
                    for (int mt = 0; mt < 4; mt++)
                        #pragma unroll
                        for (int h = 0; h < 2; h++) {
                            const int e = mt*2 + h;
                            int row = wm*64 + mt*16 + (lane >> 2) + 8*h;
                            float* m = &mrg[row*16 + wn*4];
                            m[0] = st_z[e]; m[1] = st_w0[e]; m[2] = st_w1[e]; m[3] = st_w2[e];
                        }
                }
                __syncthreads();
                if (tid < 128) {
                    int row = tid;
                    float z = 0.f, w0 = 0.f, w1 = 0.f, w2 = 0.f;
                    #pragma unroll
                    for (int w = 0; w < 4; w++) {
                        const float* m = &mrg[row*16 + w*4];
                        z += m[0]; w0 += m[1]; w1 += m[2]; w2 += m[3];
                    }
                    int b = chunk >> 1;
                    int rg = r0 + row;
                    float inv = 1.0f / z;
                    g_Tl[b*ROWS + rg] = tanhf(w0*inv + bias_l);
                    g_Ta[b*ROWS + rg] = tanhf(w1*inv + bias_a);
                    g_Tt[b*ROWS + rg] = tanhf(w2*inv + bias_t);
                }
                #pragma unroll
                for (int e = 0; e < 8; e++) {
                    st_z[e]=0.f; st_w0[e]=0.f; st_w1[e]=0.f; st_w2[e]=0.f;
                }
            }
        }
    }
}

// ---------------- reduce over r (512) per (b,l) ------------------------------
__global__ void head_reduce_kernel(const float* __restrict__ w1l, const float* __restrict__ b1l,
                                   const float* __restrict__ w1a, const float* __restrict__ b1a,
                                   const float* __restrict__ w1t, const float* __restrict__ b1t,
                                   float* __restrict__ out)
{
    int bl = blockIdx.x;
    int b = bl / LL, l = bl % LL;
    size_t base = (size_t)b*ROWS + (size_t)l*RR;
    int tid = threadIdx.x;
    float sl = 0.f, sa = 0.f, st = 0.f;
    for (int r = tid; r < RR; r += 256) {
        sl += g_Tl[base + r] * w1l[r];
        sa += g_Ta[base + r] * w1a[r];
        st += g_Tt[base + r] * w1t[r];
    }
    __shared__ float red[3][8];
    int warp = tid >> 5, lane = tid & 31;
    #pragma unroll
    for (int off = 16; off; off >>= 1) {
        sl += __shfl_xor_sync(0xffffffffu, sl, off);
        sa += __shfl_xor_sync(0xffffffffu, sa, off);
        st += __shfl_xor_sync(0xffffffffu, st, off);
    }
    if (lane == 0) { red[0][warp] = sl; red[1][warp] = sa; red[2][warp] = st; }
    __syncthreads();
    if (tid == 0) {
        float SL = 0.f, SA = 0.f, ST = 0.f;
        #pragma unroll
        for (int w = 0; w < 8; w++) { SL += red[0][w]; SA += red[1][w]; ST += red[2][w]; }
        out[b*LL + l] = SL + b1l[0];
        g_accu1v[b*LL + l] = tanhf(SA + b1a[0]);
        g_term1v[b*LL + l] = tanhf(ST + b1t[0]);
    }
}

// ---------------- final tiny classifier heads --------------------------------
__global__ void final_kernel(const float* __restrict__ Wa2, const float* __restrict__ ba2,
                             const float* __restrict__ Wt2, const float* __restrict__ bt2,
                             float* __restrict__ out)
{
    int t = threadIdx.x;
    if (t < BB*119) {
        int b = t / 119, j = t % 119;
        float s = 0.f;
        for (int l = 0; l < LL; l++) s += g_accu1v[b*LL + l] * Wa2[j*LL + l];
        out[BB*LL + b*119 + j] = s + ba2[j];
    } else if (t < BB*119 + BB*11) {
        int u = t - BB*119;
        int b = u / 11, j = u % 11;
        float s = 0.f;
        for (int l = 0; l < LL; l++) s += g_term1v[b*LL + l] * Wt2[j*LL + l];
        out[BB*LL + BB*119 + b*11 + j] = s + bt2[j];
    }
}

// ---------------- launcher ---------------------------------------------------
extern "C" void kernel_launch(void* const* d_in, const int* in_sizes, int n_in,
                              void* d_out, int out_size)
{
    const float* outp = (const float*)d_in[0];
    const int*   mask = (const int*)  d_in[1];
    const float* laws = (const float*)d_in[2];
    const float* Wq   = (const float*)d_in[3];
    const float* bq   = (const float*)d_in[4];
    const float* Wk   = (const float*)d_in[5];
    const float* bk   = (const float*)d_in[6];
    const float* Wv   = (const float*)d_in[7];
    const float* bv   = (const float*)d_in[8];
    const float* wld  = (const float*)d_in[9];
    const float* bld  = (const float*)d_in[10];
    const float* wl1  = (const float*)d_in[11];
    const float* bl1  = (const float*)d_in[12];
    const float* wad  = (const float*)d_in[13];
    const float* badp = (const float*)d_in[14];
    const float* wa1  = (const float*)d_in[15];
    const float* ba1  = (const float*)d_in[16];
    const float* Wa2  = (const float*)d_in[17];
    const float* ba2  = (const float*)d_in[18];
    const float* wtd  = (const float*)d_in[19];
    const float* btdp = (const float*)d_in[20];
    const float* wt1  = (const float*)d_in[21];
    const float* bt1  = (const float*)d_in[22];
    const float* Wt2  = (const float*)d_in[23];
    const float* bt2  = (const float*)d_in[24];
    float* out = (float*)d_out;

    cudaFuncSetAttribute(attn5_kernel, cudaFuncAttributeMaxDynamicSharedMemorySize, SMEM4);
    cudaFuncSetAttribute(prep1_kernel, cudaFuncAttributeMaxDynamicSharedMemorySize, H_SMEM);
    cudaFuncSetAttribute(prep2_kernel, cudaFuncAttributeMaxDynamicSharedMemorySize, H_SMEM);

    // 1) fp16 converts (Wq, Wk, output) + 5 matvecs
    prep0_kernel<<<2400, 256>>>(Wq, Wk, Wv, outp, bk, bq, wld, wad, wtd);
    // 2) Mt = WqF x WkF^T (HMMA, 72 tiles) + colbias (1024 blocks)
    prep1_kernel<<<1096, 256, H_SMEM>>>(outp, mask, bk, bq, bv, wld, wad, wtd);
    // 3) fk2 = inv*(outF x MtF^T + c1) (HMMA, 96 tiles)
    prep2_kernel<<<96, 256, H_SMEM>>>();
    // 4) HMMA fused scores GEMM (fp32->fp16 A convert in-kernel) + softmax heads
    attn5_kernel<<<ROWS/128, 256, SMEM4>>>(laws, bld, badp, btdp);
    // 5) reduce over r per (b,l)
    head_reduce_kernel<<<BB*LL, 256>>>(wl1, bl1, wa1, ba1, wt1, bt1, out);
    // 6) tiny classifier heads
    final_kernel<<<1, 288>>>(Wa2, ba2, Wt2, bt2, out);
}